// round 1
// baseline (speedup 1.0000x reference)
#include <cuda_runtime.h>
#include <cuda_bf16.h>
#include <math.h>

// Problem constants
#define BB 4
#define NN 1024
#define DD 1024
#define HH 16
#define DH 64
#define MLPD 4096
#define ROWS (BB*NN)          // 4096
#define EPS 1e-6f

// ---------------- scratch (device globals; no allocations allowed) ----------
__device__ float g_mod[BB * 6 * DD];          // [4, 6144]
__device__ float g_h[ROWS * DD];              // LN+modulate output (reused for h2)
__device__ float g_q[ROWS * DD];              // q
__device__ float g_kv[ROWS * 2 * DD];         // k | v
__device__ float g_ao[ROWS * DD];             // attention output (pre Wo)
__device__ float g_hid[ROWS * MLPD];          // gelu(h2 @ W1 + b1)

// ---------------- adaLN modulation: mod = silu(c) @ Wada + bada -------------
// grid (6144/256, B), block 256
__global__ void mod_kernel(const float* __restrict__ c,
                           const float* __restrict__ Wada,
                           const float* __restrict__ bada,
                           float* __restrict__ mod) {
    __shared__ float sc[DD];
    int b = blockIdx.y;
    int j = blockIdx.x * 256 + threadIdx.x;
    for (int k = threadIdx.x; k < DD; k += 256) {
        float v = c[b * DD + k];
        sc[k] = v / (1.f + __expf(-v));
    }
    __syncthreads();
    float acc = bada[j];
    #pragma unroll 4
    for (int k = 0; k < DD; k++) acc += sc[k] * Wada[(size_t)k * (6 * DD) + j];
    mod[b * (6 * DD) + j] = acc;
}

// ---------------- block reduction helper ------------------------------------
__device__ __forceinline__ float block_sum256(float v, float* sred) {
    #pragma unroll
    for (int o = 16; o > 0; o >>= 1) v += __shfl_down_sync(0xffffffffu, v, o);
    int lane = threadIdx.x & 31, w = threadIdx.x >> 5;
    if (lane == 0) sred[w] = v;
    __syncthreads();
    if (w == 0) {
        float t = (lane < 8) ? sred[lane] : 0.f;
        #pragma unroll
        for (int o = 4; o > 0; o >>= 1) t += __shfl_down_sync(0xffffffffu, t, o);
        if (lane == 0) sred[0] = t;
    }
    __syncthreads();
    float r = sred[0];
    __syncthreads();
    return r;
}

// ---------------- LayerNorm + modulate: h = ln(x)*(1+sc) + sh ---------------
// grid ROWS, block 256; each thread owns 4 contiguous cols
__global__ void ln_mod_kernel(const float* __restrict__ x,
                              const float* __restrict__ mod,
                              int segShift, int segScale,
                              float* __restrict__ h) {
    __shared__ float sred[8];
    int row = blockIdx.x;
    int b = row >> 10;
    const float* xr = x + (size_t)row * DD;
    int c0 = threadIdx.x * 4;
    float4 xv = *(const float4*)(xr + c0);
    float sum = block_sum256(xv.x + xv.y + xv.z + xv.w, sred);
    float mean = sum * (1.f / DD);
    float d0 = xv.x - mean, d1 = xv.y - mean, d2 = xv.z - mean, d3 = xv.w - mean;
    float ss = block_sum256(d0 * d0 + d1 * d1 + d2 * d2 + d3 * d3, sred);
    float rstd = rsqrtf(ss * (1.f / DD) + EPS);
    const float* shp = mod + b * (6 * DD) + segShift * DD;
    const float* scp = mod + b * (6 * DD) + segScale * DD;
    float4 shv = *(const float4*)(shp + c0);
    float4 scv = *(const float4*)(scp + c0);
    float4 hv;
    hv.x = d0 * rstd * (1.f + scv.x) + shv.x;
    hv.y = d1 * rstd * (1.f + scv.y) + shv.y;
    hv.z = d2 * rstd * (1.f + scv.z) + shv.z;
    hv.w = d3 * rstd * (1.f + scv.w) + shv.w;
    *(float4*)(h + (size_t)row * DD + c0) = hv;
}

// ---------------- tiled SGEMM: C = A[M,K] @ W[K,N] + bias, fused epilogues ---
// EPI: 0 = none, 1 = gelu(tanh), 2 = residual + gate (C = resid + gate*(acc+bias))
template <int EPI>
__global__ __launch_bounds__(256) void sgemm_kernel(
    const float* __restrict__ A, const float* __restrict__ W,
    const float* __restrict__ bias, float* __restrict__ C,
    int M, int N, int K,
    const float* __restrict__ resid, const float* __restrict__ gate) {
    __shared__ float As[8][128];
    __shared__ float Bs[8][128];
    int bm = blockIdx.y * 128, bn = blockIdx.x * 128;
    int tid = threadIdx.x;
    int arow = tid >> 1, acol = (tid & 1) * 4;      // A tile 128x8, float4/thread
    int brow = tid >> 5, bcol = (tid & 31) * 4;     // B tile 8x128, float4/thread
    int tx = tid & 15, ty = tid >> 4;               // 16x16 threads, 8x8 micro-tile
    float acc[8][8];
    #pragma unroll
    for (int i = 0; i < 8; i++)
        #pragma unroll
        for (int j = 0; j < 8; j++) acc[i][j] = 0.f;

    const float* Aptr = A + (size_t)(bm + arow) * K + acol;
    const float* Wptr = W + (size_t)brow * N + bn + bcol;

    for (int k0 = 0; k0 < K; k0 += 8) {
        float4 av = *(const float4*)Aptr; Aptr += 8;
        float4 bv = *(const float4*)Wptr; Wptr += (size_t)8 * N;
        __syncthreads();
        As[acol + 0][arow] = av.x;
        As[acol + 1][arow] = av.y;
        As[acol + 2][arow] = av.z;
        As[acol + 3][arow] = av.w;
        *(float4*)&Bs[brow][bcol] = bv;
        __syncthreads();
        #pragma unroll
        for (int kk = 0; kk < 8; kk++) {
            float af[8], bf[8];
            *(float4*)(af)     = *(const float4*)&As[kk][ty * 8];
            *(float4*)(af + 4) = *(const float4*)&As[kk][ty * 8 + 4];
            *(float4*)(bf)     = *(const float4*)&Bs[kk][tx * 8];
            *(float4*)(bf + 4) = *(const float4*)&Bs[kk][tx * 8 + 4];
            #pragma unroll
            for (int i = 0; i < 8; i++)
                #pragma unroll
                for (int j = 0; j < 8; j++)
                    acc[i][j] = fmaf(af[i], bf[j], acc[i][j]);
        }
    }

    int row0 = bm + ty * 8, col0 = bn + tx * 8;
    #pragma unroll
    for (int i = 0; i < 8; i++) {
        int row = row0 + i;
        int b = row >> 10;
        float4 o0, o1;
        float* op0 = &o0.x;
        float* op1 = &o1.x;
        #pragma unroll
        for (int j = 0; j < 8; j++) {
            int col = col0 + j;
            float v = acc[i][j] + bias[col];
            if (EPI == 1) {
                float u = v;
                v = 0.5f * u * (1.f + tanhf(0.7978845608028654f * (u + 0.044715f * u * u * u)));
            } else if (EPI == 2) {
                v = resid[(size_t)row * N + col] + gate[b * (6 * DD) + col] * v;
            }
            if (j < 4) op0[j] = v; else op1[j - 4] = v;
        }
        *(float4*)(C + (size_t)row * N + col0)     = o0;
        *(float4*)(C + (size_t)row * N + col0 + 4) = o1;
    }
}

// ---------------- flash attention (fp32, online softmax) --------------------
// grid (N/64, H, B), block 64; each thread owns one query row.
__global__ __launch_bounds__(64) void attn_kernel(const float* __restrict__ q,
                                                  const float* __restrict__ kv,
                                                  float* __restrict__ ao) {
    __shared__ float Ks[32][64];
    __shared__ float Vs[32][64];
    int b = blockIdx.z, hd = blockIdx.y, tile = blockIdx.x;
    int t = threadIdx.x;
    int qi = tile * 64 + t;
    size_t qoff = ((size_t)(b * NN + qi)) * DD + hd * DH;
    float qreg[DH];
    #pragma unroll
    for (int d4 = 0; d4 < 16; d4++) {
        float4 v4 = *(const float4*)(q + qoff + d4 * 4);
        qreg[4 * d4] = v4.x; qreg[4 * d4 + 1] = v4.y;
        qreg[4 * d4 + 2] = v4.z; qreg[4 * d4 + 3] = v4.w;
    }
    float o[DH];
    #pragma unroll
    for (int d = 0; d < DH; d++) o[d] = 0.f;
    float m = -1e30f, l = 0.f;
    const float scale = 0.125f;  // DH^-0.5

    for (int kt = 0; kt < NN; kt += 32) {
        // cooperative coalesced load of K/V tiles
        #pragma unroll 4
        for (int r = 0; r < 32; r++) {
            size_t krow = ((size_t)(b * NN + kt + r)) * (2 * DD) + hd * DH + t;
            Ks[r][t] = kv[krow];
            Vs[r][t] = kv[krow + DD];
        }
        __syncthreads();

        float s[32];
        float mt = -1e30f;
        #pragma unroll
        for (int j = 0; j < 32; j++) {
            float a = 0.f;
            const float4* kp = (const float4*)Ks[j];
            #pragma unroll
            for (int d4 = 0; d4 < 16; d4++) {
                float4 kk = kp[d4];
                a = fmaf(qreg[4 * d4], kk.x, a);
                a = fmaf(qreg[4 * d4 + 1], kk.y, a);
                a = fmaf(qreg[4 * d4 + 2], kk.z, a);
                a = fmaf(qreg[4 * d4 + 3], kk.w, a);
            }
            s[j] = a * scale;
            mt = fmaxf(mt, s[j]);
        }
        float mnew = fmaxf(m, mt);
        float corr = __expf(m - mnew);
        l *= corr;
        #pragma unroll
        for (int d = 0; d < DH; d++) o[d] *= corr;
        #pragma unroll
        for (int j = 0; j < 32; j++) {
            float p = __expf(s[j] - mnew);
            l += p;
            const float4* vp = (const float4*)Vs[j];
            #pragma unroll
            for (int d4 = 0; d4 < 16; d4++) {
                float4 vv = vp[d4];
                o[4 * d4]     = fmaf(p, vv.x, o[4 * d4]);
                o[4 * d4 + 1] = fmaf(p, vv.y, o[4 * d4 + 1]);
                o[4 * d4 + 2] = fmaf(p, vv.z, o[4 * d4 + 2]);
                o[4 * d4 + 3] = fmaf(p, vv.w, o[4 * d4 + 3]);
            }
        }
        m = mnew;
        __syncthreads();
    }
    float rl = 1.f / l;
    #pragma unroll
    for (int d4 = 0; d4 < 16; d4++) {
        float4 v4;
        v4.x = o[4 * d4] * rl; v4.y = o[4 * d4 + 1] * rl;
        v4.z = o[4 * d4 + 2] * rl; v4.w = o[4 * d4 + 3] * rl;
        *(float4*)(ao + qoff + d4 * 4) = v4;
    }
}

// ---------------- launch -----------------------------------------------------
extern "C" void kernel_launch(void* const* d_in, const int* in_sizes, int n_in,
                              void* d_out, int out_size) {
    const float* x    = (const float*)d_in[0];
    const float* c    = (const float*)d_in[1];
    const float* Wq   = (const float*)d_in[2];
    const float* bq   = (const float*)d_in[3];
    const float* Wkv  = (const float*)d_in[4];
    const float* bkv  = (const float*)d_in[5];
    const float* Wo   = (const float*)d_in[6];
    const float* bo   = (const float*)d_in[7];
    const float* W1   = (const float*)d_in[8];
    const float* b1   = (const float*)d_in[9];
    const float* W2   = (const float*)d_in[10];
    const float* b2   = (const float*)d_in[11];
    const float* Wada = (const float*)d_in[12];
    const float* bada = (const float*)d_in[13];
    float* out = (float*)d_out;

    float *mod, *h, *qb, *kvb, *ao, *hid;
    cudaGetSymbolAddress((void**)&mod, g_mod);
    cudaGetSymbolAddress((void**)&h,   g_h);
    cudaGetSymbolAddress((void**)&qb,  g_q);
    cudaGetSymbolAddress((void**)&kvb, g_kv);
    cudaGetSymbolAddress((void**)&ao,  g_ao);
    cudaGetSymbolAddress((void**)&hid, g_hid);

    // 1. adaLN modulation vectors
    mod_kernel<<<dim3(6 * DD / 256, BB), 256>>>(c, Wada, bada, mod);
    // 2. h = modulate(LN(x), sh_msa, sc_msa)   (segments 0,1)
    ln_mod_kernel<<<ROWS, 256>>>(x, mod, 0, 1, h);
    // 3. q = h @ Wq + bq
    sgemm_kernel<0><<<dim3(DD / 128, ROWS / 128), 256>>>(h, Wq, bq, qb,
        ROWS, DD, DD, nullptr, nullptr);
    // 4. kv = h @ Wkv + bkv
    sgemm_kernel<0><<<dim3(2 * DD / 128, ROWS / 128), 256>>>(h, Wkv, bkv, kvb,
        ROWS, 2 * DD, DD, nullptr, nullptr);
    // 5. attention
    attn_kernel<<<dim3(NN / 64, HH, BB), 64>>>(qb, kvb, ao);
    // 6. x1 = x + g_msa * (ao @ Wo + bo)   -> d_out   (gate segment 2)
    sgemm_kernel<2><<<dim3(DD / 128, ROWS / 128), 256>>>(ao, Wo, bo, out,
        ROWS, DD, DD, x, mod + 2 * DD);
    // 7. h2 = modulate(LN(x1), sh_mlp, sc_mlp)   (segments 3,4) -> reuse h
    ln_mod_kernel<<<ROWS, 256>>>(out, mod, 3, 4, h);
    // 8. hid = gelu(h2 @ W1 + b1)
    sgemm_kernel<1><<<dim3(MLPD / 128, ROWS / 128), 256>>>(h, W1, b1, hid,
        ROWS, MLPD, DD, nullptr, nullptr);
    // 9. out = x1 + g_mlp * (hid @ W2 + b2)   (gate segment 5), in-place on d_out
    sgemm_kernel<2><<<dim3(DD / 128, ROWS / 128), 256>>>(hid, W2, b2, out,
        ROWS, DD, MLPD, out, mod + 5 * DD);
}

// round 3
// speedup vs baseline: 2.3929x; 2.3929x over previous
#include <cuda_runtime.h>
#include <cuda_bf16.h>
#include <cstdint>
#include <math.h>

// Problem constants
#define BB 4
#define NN 1024
#define DD 1024
#define HH 16
#define DHD 64
#define MLPD 4096
#define ROWS (BB*NN)          // 4096
#define EPS 1e-6f

// GEMM tiling
#define BM 128
#define BN 256
#define BK 32
#define STG 3
#define ROWB 144              // 32 floats + 16B pad per row
#define ASTG (BM*ROWB)        // 18432
#define BSTG (BN*ROWB)        // 36864
#define STGB (ASTG+BSTG)      // 55296
#define SMEM_GEMM (STG*STGB)  // 165888

// ---------------- scratch (device globals; no allocations allowed) ----------
__device__ float g_mod[BB * 6 * DD];
__device__ float g_h[ROWS * DD];
__device__ float g_q[ROWS * DD];
__device__ float g_kv[ROWS * 2 * DD];
__device__ float g_ao[ROWS * DD];
__device__ float g_hid[ROWS * MLPD];
__device__ float g_WTq[DD * DD];
__device__ float g_WTkv[2 * DD * DD];
__device__ float g_WTo[DD * DD];
__device__ float g_WT1[MLPD * DD];
__device__ float g_WT2[DD * MLPD];

// ======================= helpers ============================================
__device__ __forceinline__ uint32_t smem_u32(const void* p) {
    uint32_t a;
    asm("{ .reg .u64 t; cvta.to.shared.u64 t, %1; cvt.u32.u64 %0, t; }"
        : "=r"(a) : "l"(p));
    return a;
}
__device__ __forceinline__ float tf32r(float x) {
    uint32_t u;
    asm("cvt.rna.tf32.f32 %0, %1;" : "=r"(u) : "f"(x));
    return __uint_as_float(u);
}
__device__ __forceinline__ void ldsm4(uint32_t* r, uint32_t addr) {
    asm volatile("ldmatrix.sync.aligned.m8n8.x4.shared.b16 {%0,%1,%2,%3}, [%4];"
                 : "=r"(r[0]), "=r"(r[1]), "=r"(r[2]), "=r"(r[3]) : "r"(addr));
}
__device__ __forceinline__ void mma8(float* c, const uint32_t* a, const uint32_t* b) {
    asm volatile(
        "mma.sync.aligned.m16n8k8.row.col.f32.tf32.tf32.f32 "
        "{%0,%1,%2,%3}, {%4,%5,%6,%7}, {%8,%9}, {%0,%1,%2,%3};"
        : "+f"(c[0]), "+f"(c[1]), "+f"(c[2]), "+f"(c[3])
        : "r"(a[0]), "r"(a[1]), "r"(a[2]), "r"(a[3]), "r"(b[0]), "r"(b[1]));
}
__device__ __forceinline__ void cp16(uint32_t dst, const void* src) {
    asm volatile("cp.async.cg.shared.global [%0], [%1], 16;"
                 :: "r"(dst), "l"(src) : "memory");
}

// ===================== weight transpose W[K,N] -> WT[N,K] (tf32-rounded) ====
__global__ void transpose_kernel(const float* __restrict__ W, float* __restrict__ WT,
                                 int K, int N) {
    __shared__ float t[32][33];
    int n0 = blockIdx.x * 32, k0 = blockIdx.y * 32;
    int tx = threadIdx.x, ty = threadIdx.y;  // 32 x 8
    #pragma unroll
    for (int i = 0; i < 32; i += 8)
        t[ty + i][tx] = tf32r(W[(size_t)(k0 + ty + i) * N + n0 + tx]);
    __syncthreads();
    #pragma unroll
    for (int i = 0; i < 32; i += 8)
        WT[(size_t)(n0 + ty + i) * K + k0 + tx] = t[tx][ty + i];
}

// ============ tf32 mma.sync GEMM: C = A[M,K] @ BT[N,K]^T + bias =============
// Inputs A and BT must already be tf32-rounded.
// EPI: 0 none, 1 gelu(tanh) + tf32-round output, 2 residual + gate
template <int EPI>
__global__ __launch_bounds__(256)
void mma_gemm(const float* __restrict__ A, const float* __restrict__ BT,
              const float* __restrict__ bias, float* __restrict__ C,
              int M, int N, int K,
              const float* __restrict__ resid, const float* __restrict__ gate) {
    extern __shared__ char smem[];
    uint32_t sb = smem_u32(smem);
    int tid = threadIdx.x, lane = tid & 31, wid = tid >> 5;
    int wm = wid & 1, wn = wid >> 1;            // 2 x 4 warp grid, 64x64 each
    int bm = blockIdx.y * BM, bn = blockIdx.x * BN;

    float acc[4][8][4];
    #pragma unroll
    for (int i = 0; i < 4; i++)
        #pragma unroll
        for (int j = 0; j < 8; j++)
            #pragma unroll
            for (int e = 0; e < 4; e++) acc[i][j][e] = 0.f;

    // ldmatrix per-lane address components
    int r8 = lane & 7;
    uint32_t a_off = (uint32_t)((wm * 64 + ((lane >> 3) & 1) * 8 + r8) * ROWB
                                + (lane >> 4) * 16);
    uint32_t b_off = (uint32_t)((wn * 64 + (lane >> 4) * 8 + r8) * ROWB
                                + ((lane >> 3) & 1) * 16);

    const int nst = K / BK;

    // cp.async stage loader
    auto load_stage = [&](int s, int buf) {
        uint32_t ab = sb + buf * STGB;
        uint32_t bb = ab + ASTG;
        int ko = s * BK;
        #pragma unroll
        for (int i = 0; i < 4; i++) {
            int idx = tid + 256 * i, row = idx >> 3, c = idx & 7;
            cp16(ab + row * ROWB + c * 16, A + (size_t)(bm + row) * K + ko + c * 4);
        }
        #pragma unroll
        for (int i = 0; i < 8; i++) {
            int idx = tid + 256 * i, row = idx >> 3, c = idx & 7;
            cp16(bb + row * ROWB + c * 16, BT + (size_t)(bn + row) * K + ko + c * 4);
        }
    };

    load_stage(0, 0);
    asm volatile("cp.async.commit_group;" ::: "memory");
    load_stage(1, 1);
    asm volatile("cp.async.commit_group;" ::: "memory");

    for (int s = 0; s < nst; s++) {
        asm volatile("cp.async.wait_group 1;" ::: "memory");
        __syncthreads();
        if (s + 2 < nst) load_stage(s + 2, (s + 2) % STG);
        asm volatile("cp.async.commit_group;" ::: "memory");

        uint32_t ab = sb + (s % STG) * STGB;
        uint32_t bb = ab + ASTG;
        #pragma unroll
        for (int ks = 0; ks < 4; ks++) {
            uint32_t afr[4][4], bfr[4][4];
            #pragma unroll
            for (int i = 0; i < 4; i++)
                ldsm4(afr[i], ab + a_off + i * 16 * ROWB + ks * 32);
            #pragma unroll
            for (int jp = 0; jp < 4; jp++)
                ldsm4(bfr[jp], bb + b_off + jp * 16 * ROWB + ks * 32);
            #pragma unroll
            for (int i = 0; i < 4; i++)
                #pragma unroll
                for (int j = 0; j < 8; j++)
                    mma8(acc[i][j], afr[i], &bfr[j >> 1][(j & 1) * 2]);
        }
    }

    // ---------------- epilogue ----------------
    int g = lane >> 2, tg = lane & 3;
    #pragma unroll
    for (int i = 0; i < 4; i++) {
        #pragma unroll
        for (int half = 0; half < 2; half++) {
            int row = bm + wm * 64 + i * 16 + half * 8 + g;
            int bvar = row >> 10;
            #pragma unroll
            for (int j = 0; j < 8; j++) {
                int col = bn + wn * 64 + j * 8 + tg * 2;
                float v0 = acc[i][j][half * 2 + 0] + bias[col];
                float v1 = acc[i][j][half * 2 + 1] + bias[col + 1];
                if (EPI == 1) {
                    float u = v0;
                    v0 = tf32r(0.5f * u * (1.f + tanhf(0.7978845608028654f *
                                                       (u + 0.044715f * u * u * u))));
                    u = v1;
                    v1 = tf32r(0.5f * u * (1.f + tanhf(0.7978845608028654f *
                                                       (u + 0.044715f * u * u * u))));
                } else if (EPI == 2) {
                    float2 rv = *(const float2*)(resid + (size_t)row * N + col);
                    float2 gv = *(const float2*)(gate + bvar * (6 * DD) + col);
                    v0 = rv.x + gv.x * v0;
                    v1 = rv.y + gv.y * v1;
                }
                float2 o = make_float2(v0, v1);
                *(float2*)(C + (size_t)row * N + col) = o;
            }
        }
    }
}

// ---------------- adaLN modulation: mod = silu(c) @ Wada + bada -------------
__global__ void mod_kernel(const float* __restrict__ c,
                           const float* __restrict__ Wada,
                           const float* __restrict__ bada,
                           float* __restrict__ mod) {
    __shared__ float sc[DD];
    int b = blockIdx.y;
    int j = blockIdx.x * 256 + threadIdx.x;
    for (int k = threadIdx.x; k < DD; k += 256) {
        float v = c[b * DD + k];
        sc[k] = v / (1.f + __expf(-v));
    }
    __syncthreads();
    float acc = bada[j];
    #pragma unroll 4
    for (int k = 0; k < DD; k++) acc += sc[k] * Wada[(size_t)k * (6 * DD) + j];
    mod[b * (6 * DD) + j] = acc;
}

// ---------------- LayerNorm + modulate (tf32-rounded output) -----------------
__device__ __forceinline__ float block_sum256(float v, float* sred) {
    #pragma unroll
    for (int o = 16; o > 0; o >>= 1) v += __shfl_down_sync(0xffffffffu, v, o);
    int lane = threadIdx.x & 31, w = threadIdx.x >> 5;
    if (lane == 0) sred[w] = v;
    __syncthreads();
    if (w == 0) {
        float t = (lane < 8) ? sred[lane] : 0.f;
        #pragma unroll
        for (int o = 4; o > 0; o >>= 1) t += __shfl_down_sync(0xffffffffu, t, o);
        if (lane == 0) sred[0] = t;
    }
    __syncthreads();
    float r = sred[0];
    __syncthreads();
    return r;
}

__global__ void ln_mod_kernel(const float* __restrict__ x,
                              const float* __restrict__ mod,
                              int segShift, int segScale,
                              float* __restrict__ h) {
    __shared__ float sred[8];
    int row = blockIdx.x;
    int b = row >> 10;
    const float* xr = x + (size_t)row * DD;
    int c0 = threadIdx.x * 4;
    float4 xv = *(const float4*)(xr + c0);
    float sum = block_sum256(xv.x + xv.y + xv.z + xv.w, sred);
    float mean = sum * (1.f / DD);
    float d0 = xv.x - mean, d1 = xv.y - mean, d2 = xv.z - mean, d3 = xv.w - mean;
    float ss = block_sum256(d0 * d0 + d1 * d1 + d2 * d2 + d3 * d3, sred);
    float rstd = rsqrtf(ss * (1.f / DD) + EPS);
    const float* shp = mod + b * (6 * DD) + segShift * DD;
    const float* scp = mod + b * (6 * DD) + segScale * DD;
    float4 shv = *(const float4*)(shp + c0);
    float4 scv = *(const float4*)(scp + c0);
    float4 hv;
    hv.x = tf32r(d0 * rstd * (1.f + scv.x) + shv.x);
    hv.y = tf32r(d1 * rstd * (1.f + scv.y) + shv.y);
    hv.z = tf32r(d2 * rstd * (1.f + scv.z) + shv.z);
    hv.w = tf32r(d3 * rstd * (1.f + scv.w) + shv.w);
    *(float4*)(h + (size_t)row * DD + c0) = hv;
}

// ---------------- flash attention (fp32, online softmax) --------------------
__global__ __launch_bounds__(64) void attn_kernel(const float* __restrict__ q,
                                                  const float* __restrict__ kv,
                                                  float* __restrict__ ao) {
    __shared__ float Ks[32][64];
    __shared__ float Vs[32][64];
    int b = blockIdx.z, hd = blockIdx.y, tile = blockIdx.x;
    int t = threadIdx.x;
    int qi = tile * 64 + t;
    size_t qoff = ((size_t)(b * NN + qi)) * DD + hd * DHD;
    float qreg[DHD];
    #pragma unroll
    for (int d4 = 0; d4 < 16; d4++) {
        float4 v4 = *(const float4*)(q + qoff + d4 * 4);
        qreg[4 * d4] = v4.x; qreg[4 * d4 + 1] = v4.y;
        qreg[4 * d4 + 2] = v4.z; qreg[4 * d4 + 3] = v4.w;
    }
    float o[DHD];
    #pragma unroll
    for (int d = 0; d < DHD; d++) o[d] = 0.f;
    float m = -1e30f, l = 0.f;
    const float scale = 0.125f;

    for (int kt = 0; kt < NN; kt += 32) {
        #pragma unroll 4
        for (int r = 0; r < 32; r++) {
            size_t krow = ((size_t)(b * NN + kt + r)) * (2 * DD) + hd * DHD + t;
            Ks[r][t] = kv[krow];
            Vs[r][t] = kv[krow + DD];
        }
        __syncthreads();

        float s[32];
        float mt = -1e30f;
        #pragma unroll
        for (int j = 0; j < 32; j++) {
            float a = 0.f;
            const float4* kp = (const float4*)Ks[j];
            #pragma unroll
            for (int d4 = 0; d4 < 16; d4++) {
                float4 kk = kp[d4];
                a = fmaf(qreg[4 * d4], kk.x, a);
                a = fmaf(qreg[4 * d4 + 1], kk.y, a);
                a = fmaf(qreg[4 * d4 + 2], kk.z, a);
                a = fmaf(qreg[4 * d4 + 3], kk.w, a);
            }
            s[j] = a * scale;
            mt = fmaxf(mt, s[j]);
        }
        float mnew = fmaxf(m, mt);
        float corr = __expf(m - mnew);
        l *= corr;
        #pragma unroll
        for (int d = 0; d < DHD; d++) o[d] *= corr;
        #pragma unroll
        for (int j = 0; j < 32; j++) {
            float p = __expf(s[j] - mnew);
            l += p;
            const float4* vp = (const float4*)Vs[j];
            #pragma unroll
            for (int d4 = 0; d4 < 16; d4++) {
                float4 vv = vp[d4];
                o[4 * d4]     = fmaf(p, vv.x, o[4 * d4]);
                o[4 * d4 + 1] = fmaf(p, vv.y, o[4 * d4 + 1]);
                o[4 * d4 + 2] = fmaf(p, vv.z, o[4 * d4 + 2]);
                o[4 * d4 + 3] = fmaf(p, vv.w, o[4 * d4 + 3]);
            }
        }
        m = mnew;
        __syncthreads();
    }
    float rl = 1.f / l;
    #pragma unroll
    for (int d4 = 0; d4 < 16; d4++) {
        float4 v4;
        v4.x = tf32r(o[4 * d4] * rl);     v4.y = tf32r(o[4 * d4 + 1] * rl);
        v4.z = tf32r(o[4 * d4 + 2] * rl); v4.w = tf32r(o[4 * d4 + 3] * rl);
        *(float4*)(ao + qoff + d4 * 4) = v4;
    }
}

// ---------------- launch -----------------------------------------------------
extern "C" void kernel_launch(void* const* d_in, const int* in_sizes, int n_in,
                              void* d_out, int out_size) {
    const float* x    = (const float*)d_in[0];
    const float* c    = (const float*)d_in[1];
    const float* Wq   = (const float*)d_in[2];
    const float* bq   = (const float*)d_in[3];
    const float* Wkv  = (const float*)d_in[4];
    const float* bkv  = (const float*)d_in[5];
    const float* Wo   = (const float*)d_in[6];
    const float* bo   = (const float*)d_in[7];
    const float* W1   = (const float*)d_in[8];
    const float* b1   = (const float*)d_in[9];
    const float* W2   = (const float*)d_in[10];
    const float* b2   = (const float*)d_in[11];
    const float* Wada = (const float*)d_in[12];
    const float* bada = (const float*)d_in[13];
    float* out = (float*)d_out;

    float *mod, *h, *qb, *kvb, *ao, *hid, *WTq, *WTkv, *WTo, *WT1, *WT2;
    cudaGetSymbolAddress((void**)&mod,  g_mod);
    cudaGetSymbolAddress((void**)&h,    g_h);
    cudaGetSymbolAddress((void**)&qb,   g_q);
    cudaGetSymbolAddress((void**)&kvb,  g_kv);
    cudaGetSymbolAddress((void**)&ao,   g_ao);
    cudaGetSymbolAddress((void**)&hid,  g_hid);
    cudaGetSymbolAddress((void**)&WTq,  g_WTq);
    cudaGetSymbolAddress((void**)&WTkv, g_WTkv);
    cudaGetSymbolAddress((void**)&WTo,  g_WTo);
    cudaGetSymbolAddress((void**)&WT1,  g_WT1);
    cudaGetSymbolAddress((void**)&WT2,  g_WT2);

    cudaFuncSetAttribute(mma_gemm<0>, cudaFuncAttributeMaxDynamicSharedMemorySize, SMEM_GEMM);
    cudaFuncSetAttribute(mma_gemm<1>, cudaFuncAttributeMaxDynamicSharedMemorySize, SMEM_GEMM);
    cudaFuncSetAttribute(mma_gemm<2>, cudaFuncAttributeMaxDynamicSharedMemorySize, SMEM_GEMM);

    dim3 tb(32, 8);
    transpose_kernel<<<dim3(DD / 32, DD / 32), tb>>>(Wq, WTq, DD, DD);
    transpose_kernel<<<dim3(2 * DD / 32, DD / 32), tb>>>(Wkv, WTkv, DD, 2 * DD);
    transpose_kernel<<<dim3(DD / 32, DD / 32), tb>>>(Wo, WTo, DD, DD);
    transpose_kernel<<<dim3(MLPD / 32, DD / 32), tb>>>(W1, WT1, DD, MLPD);
    transpose_kernel<<<dim3(DD / 32, MLPD / 32), tb>>>(W2, WT2, MLPD, DD);

    // 1. adaLN modulation
    mod_kernel<<<dim3(6 * DD / 256, BB), 256>>>(c, Wada, bada, mod);
    // 2. h = modulate(LN(x))   (tf32-rounded)
    ln_mod_kernel<<<ROWS, 256>>>(x, mod, 0, 1, h);
    // 3. q = h @ Wq + bq
    mma_gemm<0><<<dim3(DD / BN, ROWS / BM), 256, SMEM_GEMM>>>(
        h, WTq, bq, qb, ROWS, DD, DD, nullptr, nullptr);
    // 4. kv = h @ Wkv + bkv
    mma_gemm<0><<<dim3(2 * DD / BN, ROWS / BM), 256, SMEM_GEMM>>>(
        h, WTkv, bkv, kvb, ROWS, 2 * DD, DD, nullptr, nullptr);
    // 5. attention (fp32, tf32-rounded output)
    attn_kernel<<<dim3(NN / 64, HH, BB), 64>>>(qb, kvb, ao);
    // 6. x1 = x + g_msa * (ao @ Wo + bo) -> out
    mma_gemm<2><<<dim3(DD / BN, ROWS / BM), 256, SMEM_GEMM>>>(
        ao, WTo, bo, out, ROWS, DD, DD, x, mod + 2 * DD);
    // 7. h2 = modulate(LN(x1))
    ln_mod_kernel<<<ROWS, 256>>>(out, mod, 3, 4, h);
    // 8. hid = gelu(h2 @ W1 + b1)   (tf32-rounded)
    mma_gemm<1><<<dim3(MLPD / BN, ROWS / BM), 256, SMEM_GEMM>>>(
        h, WT1, b1, hid, ROWS, MLPD, DD, nullptr, nullptr);
    // 9. out = x1 + g_mlp * (hid @ W2 + b2)
    mma_gemm<2><<<dim3(DD / BN, ROWS / BM), 256, SMEM_GEMM>>>(
        hid, WT2, b2, out, ROWS, DD, MLPD, out, mod + 5 * DD);
}

// round 6
// speedup vs baseline: 3.9006x; 1.6300x over previous
#include <cuda_runtime.h>
#include <cuda_bf16.h>
#include <cstdint>
#include <math.h>

// Problem constants
#define BB 4
#define NN 1024
#define DD 1024
#define HH 16
#define DHD 64
#define MLPD 4096
#define ROWS (BB*NN)          // 4096
#define EPS 1e-6f

// GEMM tiling
#define BM 128
#define BN 256
#define BK 32
#define STG 3
#define ROWB 144              // 32 floats + 16B pad per row
#define ASTG (BM*ROWB)
#define BSTG (BN*ROWB)
#define STGB (ASTG+BSTG)
#define SMEM_GEMM (STG*STGB)  // 165888

// Attention tiling
#define AROWB 272             // 64 floats + 16B pad
#define ASM_Q 0
#define ASM_P 17408
#define ASM_K 34816
#define ASM_V 69632
#define SMEM_ATTN 104448

// ---------------- scratch (device globals) ----------------------------------
__device__ float g_mod[BB * 6 * DD];
__device__ float g_h[ROWS * DD];
__device__ float g_q[ROWS * DD];
__device__ float g_kv[ROWS * 2 * DD];
__device__ float g_vt[BB * HH * DHD * NN];   // V^T: [b][h][dh][key]
__device__ float g_ao[ROWS * DD];
__device__ float g_hid[ROWS * MLPD];
__device__ float g_WTq[DD * DD];
__device__ float g_WTkv[2 * DD * DD];
__device__ float g_WTo[DD * DD];
__device__ float g_WT1[MLPD * DD];
__device__ float g_WT2[DD * MLPD];

// ======================= helpers ============================================
__device__ __forceinline__ uint32_t smem_u32(const void* p) {
    uint32_t a;
    asm("{ .reg .u64 t; cvta.to.shared.u64 t, %1; cvt.u32.u64 %0, t; }"
        : "=r"(a) : "l"(p));
    return a;
}
__device__ __forceinline__ float tf32r(float x) {
    uint32_t u;
    asm("cvt.rna.tf32.f32 %0, %1;" : "=r"(u) : "f"(x));
    return __uint_as_float(u);
}
__device__ __forceinline__ float ex2(float x) {
    float r;
    asm("ex2.approx.ftz.f32 %0, %1;" : "=f"(r) : "f"(x));
    return r;
}
__device__ __forceinline__ void ldsm4(uint32_t* r, uint32_t addr) {
    asm volatile("ldmatrix.sync.aligned.m8n8.x4.shared.b16 {%0,%1,%2,%3}, [%4];"
                 : "=r"(r[0]), "=r"(r[1]), "=r"(r[2]), "=r"(r[3]) : "r"(addr));
}
__device__ __forceinline__ void mma8(float* c, const uint32_t* a, const uint32_t* b) {
    asm volatile(
        "mma.sync.aligned.m16n8k8.row.col.f32.tf32.tf32.f32 "
        "{%0,%1,%2,%3}, {%4,%5,%6,%7}, {%8,%9}, {%0,%1,%2,%3};"
        : "+f"(c[0]), "+f"(c[1]), "+f"(c[2]), "+f"(c[3])
        : "r"(a[0]), "r"(a[1]), "r"(a[2]), "r"(a[3]), "r"(b[0]), "r"(b[1]));
}
__device__ __forceinline__ void cp16(uint32_t dst, const void* src) {
    asm volatile("cp.async.cg.shared.global [%0], [%1], 16;"
                 :: "r"(dst), "l"(src) : "memory");
}

// ===================== weight transpose W[K,N] -> WT[N,K] (tf32-rounded) ====
__global__ void transpose_kernel(const float* __restrict__ W, float* __restrict__ WT,
                                 int K, int N) {
    __shared__ float t[32][33];
    int n0 = blockIdx.x * 32, k0 = blockIdx.y * 32;
    int tx = threadIdx.x, ty = threadIdx.y;  // 32 x 8
    #pragma unroll
    for (int i = 0; i < 32; i += 8)
        t[ty + i][tx] = tf32r(W[(size_t)(k0 + ty + i) * N + n0 + tx]);
    __syncthreads();
    #pragma unroll
    for (int i = 0; i < 32; i += 8)
        WT[(size_t)(n0 + ty + i) * K + k0 + tx] = t[tx][ty + i];
}

// ============ V^T extraction: kv[b*N+key][D + h*64 + dh] -> Vt[b,h,dh][key] ==
__global__ void vtrans_kernel(const float* __restrict__ kv, float* __restrict__ Vt) {
    __shared__ float t[32][33];
    int bh = blockIdx.z, b = bh >> 4, hh = bh & 15;
    int k0 = blockIdx.x * 32, d0 = blockIdx.y * 32;
    int tx = threadIdx.x, ty = threadIdx.y;
    #pragma unroll
    for (int i = 0; i < 32; i += 8)
        t[ty + i][tx] = kv[(size_t)(b * NN + k0 + ty + i) * (2 * DD) + DD + hh * 64 + d0 + tx];
    __syncthreads();
    #pragma unroll
    for (int i = 0; i < 32; i += 8)
        Vt[(size_t)(bh * 64 + d0 + ty + i) * NN + k0 + tx] = t[tx][ty + i];
}

// ============ tf32 mma.sync GEMM: C = A[M,K] @ BT[N,K]^T + bias =============
// EPI: 0 none, 1 gelu+round, 2 residual+gate, 3 round
template <int EPI>
__global__ __launch_bounds__(256)
void mma_gemm(const float* __restrict__ A, const float* __restrict__ BT,
              const float* __restrict__ bias, float* __restrict__ C,
              int M, int N, int K,
              const float* __restrict__ resid, const float* __restrict__ gate) {
    extern __shared__ char smem[];
    uint32_t sb = smem_u32(smem);
    int tid = threadIdx.x, lane = tid & 31, wid = tid >> 5;
    int wm = wid & 1, wn = wid >> 1;
    int bm = blockIdx.y * BM, bn = blockIdx.x * BN;

    float acc[4][8][4];
    #pragma unroll
    for (int i = 0; i < 4; i++)
        #pragma unroll
        for (int j = 0; j < 8; j++)
            #pragma unroll
            for (int e = 0; e < 4; e++) acc[i][j][e] = 0.f;

    int r8 = lane & 7;
    uint32_t a_off = (uint32_t)((wm * 64 + ((lane >> 3) & 1) * 8 + r8) * ROWB
                                + (lane >> 4) * 16);
    uint32_t b_off = (uint32_t)((wn * 64 + (lane >> 4) * 8 + r8) * ROWB
                                + ((lane >> 3) & 1) * 16);
    const int nst = K / BK;

    auto load_stage = [&](int s, int buf) {
        uint32_t ab = sb + buf * STGB;
        uint32_t bb = ab + ASTG;
        int ko = s * BK;
        #pragma unroll
        for (int i = 0; i < 4; i++) {
            int idx = tid + 256 * i, row = idx >> 3, c = idx & 7;
            cp16(ab + row * ROWB + c * 16, A + (size_t)(bm + row) * K + ko + c * 4);
        }
        #pragma unroll
        for (int i = 0; i < 8; i++) {
            int idx = tid + 256 * i, row = idx >> 3, c = idx & 7;
            cp16(bb + row * ROWB + c * 16, BT + (size_t)(bn + row) * K + ko + c * 4);
        }
    };

    load_stage(0, 0);
    asm volatile("cp.async.commit_group;" ::: "memory");
    load_stage(1, 1);
    asm volatile("cp.async.commit_group;" ::: "memory");

    for (int s = 0; s < nst; s++) {
        asm volatile("cp.async.wait_group 1;" ::: "memory");
        __syncthreads();
        if (s + 2 < nst) load_stage(s + 2, (s + 2) % STG);
        asm volatile("cp.async.commit_group;" ::: "memory");

        uint32_t ab = sb + (s % STG) * STGB;
        uint32_t bb = ab + ASTG;
        #pragma unroll
        for (int ks = 0; ks < 4; ks++) {
            uint32_t afr[4][4], bfr[4][4];
            #pragma unroll
            for (int i = 0; i < 4; i++)
                ldsm4(afr[i], ab + a_off + i * 16 * ROWB + ks * 32);
            #pragma unroll
            for (int jp = 0; jp < 4; jp++)
                ldsm4(bfr[jp], bb + b_off + jp * 16 * ROWB + ks * 32);
            #pragma unroll
            for (int i = 0; i < 4; i++)
                #pragma unroll
                for (int j = 0; j < 8; j++)
                    mma8(acc[i][j], afr[i], &bfr[j >> 1][(j & 1) * 2]);
        }
    }

    int g = lane >> 2, tg = lane & 3;
    #pragma unroll
    for (int i = 0; i < 4; i++) {
        #pragma unroll
        for (int half = 0; half < 2; half++) {
            int row = bm + wm * 64 + i * 16 + half * 8 + g;
            int bvar = row >> 10;
            #pragma unroll
            for (int j = 0; j < 8; j++) {
                int col = bn + wn * 64 + j * 8 + tg * 2;
                float v0 = acc[i][j][half * 2 + 0] + bias[col];
                float v1 = acc[i][j][half * 2 + 1] + bias[col + 1];
                if (EPI == 1) {
                    float u = v0;
                    v0 = tf32r(0.5f * u * (1.f + tanhf(0.7978845608028654f *
                                                       (u + 0.044715f * u * u * u))));
                    u = v1;
                    v1 = tf32r(0.5f * u * (1.f + tanhf(0.7978845608028654f *
                                                       (u + 0.044715f * u * u * u))));
                } else if (EPI == 2) {
                    float2 rv = *(const float2*)(resid + (size_t)row * N + col);
                    float2 gv = *(const float2*)(gate + bvar * (6 * DD) + col);
                    v0 = rv.x + gv.x * v0;
                    v1 = rv.y + gv.y * v1;
                } else if (EPI == 3) {
                    v0 = tf32r(v0);
                    v1 = tf32r(v1);
                }
                *(float2*)(C + (size_t)row * N + col) = make_float2(v0, v1);
            }
        }
    }
}

// =================== tf32 mma flash attention ===============================
// grid (N/64, H, B), block 128 (4 warps, 16 query rows each)
__global__ __launch_bounds__(128, 1)
void attn_mma_kernel(const float* __restrict__ q, const float* __restrict__ kv,
                     const float* __restrict__ Vt, float* __restrict__ ao) {
    extern __shared__ char smem[];
    uint32_t sb = smem_u32(smem);
    int tid = threadIdx.x, lane = tid & 31, w = tid >> 5;
    int b = blockIdx.z, hh = blockIdx.y, q0 = blockIdx.x * 64;
    int g = lane >> 2, tg = lane & 3, r8 = lane & 7;

    // Q tile load (group 0, together with K/V tile 0)
    const float* qbase = q + ((size_t)(b * NN + q0)) * DD + hh * 64;
    #pragma unroll
    for (int i = 0; i < 8; i++) {
        int u = tid + 128 * i;
        int row = u >> 4, c16 = u & 15;
        cp16(sb + ASM_Q + row * AROWB + c16 * 16, qbase + (size_t)row * DD + c16 * 4);
    }
    auto load_tile = [&](int t, int buf) {
        const float* kbase = kv + ((size_t)(b * NN + t * 64)) * (2 * DD) + hh * 64;
        const float* vbase = Vt + ((size_t)((b * HH + hh) * 64)) * NN + t * 64;
        #pragma unroll
        for (int i = 0; i < 8; i++) {
            int u = tid + 128 * i;
            int row = u >> 4, c16 = u & 15;
            cp16(sb + ASM_K + buf * 17408 + row * AROWB + c16 * 16,
                 kbase + (size_t)row * (2 * DD) + c16 * 4);
            cp16(sb + ASM_V + buf * 17408 + row * AROWB + c16 * 16,
                 vbase + (size_t)row * NN + c16 * 4);
        }
    };
    load_tile(0, 0);
    asm volatile("cp.async.commit_group;" ::: "memory");
    load_tile(1, 1);
    asm volatile("cp.async.commit_group;" ::: "memory");

    uint32_t a_pat = (uint32_t)(((((lane >> 3) & 1) * 8 + r8)) * AROWB + (lane >> 4) * 16);
    uint32_t q_off = sb + ASM_Q + w * 16 * AROWB + a_pat;
    uint32_t p_off = sb + ASM_P + w * 16 * AROWB + a_pat;
    uint32_t b_pat = (uint32_t)(((lane >> 4) * 8 + r8) * AROWB + ((lane >> 3) & 1) * 16);

    uint32_t afrQ[8][4];
    float oacc[8][4];
    #pragma unroll
    for (int j = 0; j < 8; j++)
        #pragma unroll
        for (int e = 0; e < 4; e++) oacc[j][e] = 0.f;
    float m0 = -1e30f, m1 = -1e30f, l0 = 0.f, l1 = 0.f;
    const float cc = 0.18033688011112042f;  // 0.125 * log2(e)

    for (int t = 0; t < NN / 64; t++) {
        asm volatile("cp.async.wait_group 1;" ::: "memory");
        __syncthreads();
        if (t == 0) {
            #pragma unroll
            for (int ks = 0; ks < 8; ks++) ldsm4(afrQ[ks], q_off + ks * 32);
        }
        uint32_t kb = sb + ASM_K + (t & 1) * 17408;
        uint32_t vb = sb + ASM_V + (t & 1) * 17408;

        // S = Q @ K^T
        float sacc[8][4];
        #pragma unroll
        for (int j = 0; j < 8; j++)
            #pragma unroll
            for (int e = 0; e < 4; e++) sacc[j][e] = 0.f;
        #pragma unroll
        for (int ks = 0; ks < 8; ks++) {
            #pragma unroll
            for (int jp = 0; jp < 4; jp++) {
                uint32_t bfr[4];
                ldsm4(bfr, kb + b_pat + jp * 16 * AROWB + ks * 32);
                mma8(sacc[jp * 2], afrQ[ks], bfr);
                mma8(sacc[jp * 2 + 1], afrQ[ks], bfr + 2);
            }
        }

        // online softmax (base-2)
        float mt0 = -1e30f, mt1 = -1e30f;
        #pragma unroll
        for (int j = 0; j < 8; j++) {
            mt0 = fmaxf(mt0, fmaxf(sacc[j][0], sacc[j][1]));
            mt1 = fmaxf(mt1, fmaxf(sacc[j][2], sacc[j][3]));
        }
        mt0 = fmaxf(mt0, __shfl_xor_sync(0xffffffffu, mt0, 1));
        mt0 = fmaxf(mt0, __shfl_xor_sync(0xffffffffu, mt0, 2));
        mt1 = fmaxf(mt1, __shfl_xor_sync(0xffffffffu, mt1, 1));
        mt1 = fmaxf(mt1, __shfl_xor_sync(0xffffffffu, mt1, 2));
        mt0 *= cc; mt1 *= cc;
        float mn0 = fmaxf(m0, mt0), mn1 = fmaxf(m1, mt1);
        float cor0 = ex2(m0 - mn0), cor1 = ex2(m1 - mn1);
        l0 *= cor0; l1 *= cor1;
        #pragma unroll
        for (int j = 0; j < 8; j++) {
            oacc[j][0] *= cor0; oacc[j][1] *= cor0;
            oacc[j][2] *= cor1; oacc[j][3] *= cor1;
        }
        float s0 = 0.f, s1 = 0.f;
        char* pst = smem + ASM_P + (w * 16 + g) * AROWB + tg * 8;
        #pragma unroll
        for (int j = 0; j < 8; j++) {
            float p00 = ex2(fmaf(sacc[j][0], cc, -mn0));
            float p01 = ex2(fmaf(sacc[j][1], cc, -mn0));
            float p10 = ex2(fmaf(sacc[j][2], cc, -mn1));
            float p11 = ex2(fmaf(sacc[j][3], cc, -mn1));
            s0 += p00 + p01; s1 += p10 + p11;
            *(float2*)(pst + j * 32) = make_float2(tf32r(p00), tf32r(p01));
            *(float2*)(pst + 8 * AROWB + j * 32) = make_float2(tf32r(p10), tf32r(p11));
        }
        s0 += __shfl_xor_sync(0xffffffffu, s0, 1);
        s0 += __shfl_xor_sync(0xffffffffu, s0, 2);
        s1 += __shfl_xor_sync(0xffffffffu, s1, 1);
        s1 += __shfl_xor_sync(0xffffffffu, s1, 2);
        l0 += s0; l1 += s1;
        m0 = mn0; m1 = mn1;
        __syncwarp();

        // O += P @ V^T
        #pragma unroll
        for (int ks = 0; ks < 8; ks++) {
            uint32_t aP[4];
            ldsm4(aP, p_off + ks * 32);
            #pragma unroll
            for (int jp = 0; jp < 4; jp++) {
                uint32_t bfr[4];
                ldsm4(bfr, vb + b_pat + jp * 16 * AROWB + ks * 32);
                mma8(oacc[jp * 2], aP, bfr);
                mma8(oacc[jp * 2 + 1], aP, bfr + 2);
            }
        }
        __syncthreads();
        if (t + 2 < NN / 64) load_tile(t + 2, t & 1);
        asm volatile("cp.async.commit_group;" ::: "memory");
    }

    float rl0 = 1.f / l0, rl1 = 1.f / l1;
    float* aob = ao + ((size_t)(b * NN + q0 + w * 16)) * DD + hh * 64;
    #pragma unroll
    for (int j = 0; j < 8; j++) {
        int col = j * 8 + tg * 2;
        *(float2*)(aob + (size_t)g * DD + col) =
            make_float2(tf32r(oacc[j][0] * rl0), tf32r(oacc[j][1] * rl0));
        *(float2*)(aob + (size_t)(g + 8) * DD + col) =
            make_float2(tf32r(oacc[j][2] * rl1), tf32r(oacc[j][3] * rl1));
    }
}

// ---------------- adaLN modulation ------------------------------------------
__global__ void mod_kernel(const float* __restrict__ c,
                           const float* __restrict__ Wada,
                           const float* __restrict__ bada,
                           float* __restrict__ mod) {
    __shared__ float sc[DD];
    int b = blockIdx.y;
    int j = blockIdx.x * 256 + threadIdx.x;
    for (int k = threadIdx.x; k < DD; k += 256) {
        float v = c[b * DD + k];
        sc[k] = v / (1.f + __expf(-v));
    }
    __syncthreads();
    float acc = bada[j];
    #pragma unroll 4
    for (int k = 0; k < DD; k++) acc += sc[k] * Wada[(size_t)k * (6 * DD) + j];
    mod[b * (6 * DD) + j] = acc;
}

// ---------------- LayerNorm + modulate (tf32-rounded output) -----------------
__device__ __forceinline__ float block_sum256(float v, float* sred) {
    #pragma unroll
    for (int o = 16; o > 0; o >>= 1) v += __shfl_down_sync(0xffffffffu, v, o);
    int lane = threadIdx.x & 31, w = threadIdx.x >> 5;
    if (lane == 0) sred[w] = v;
    __syncthreads();
    if (w == 0) {
        float t = (lane < 8) ? sred[lane] : 0.f;
        #pragma unroll
        for (int o = 4; o > 0; o >>= 1) t += __shfl_down_sync(0xffffffffu, t, o);
        if (lane == 0) sred[0] = t;
    }
    __syncthreads();
    float r = sred[0];
    __syncthreads();
    return r;
}

__global__ void ln_mod_kernel(const float* __restrict__ x,
                              const float* __restrict__ mod,
                              int segShift, int segScale,
                              float* __restrict__ h) {
    __shared__ float sred[8];
    int row = blockIdx.x;
    int b = row >> 10;
    const float* xr = x + (size_t)row * DD;
    int c0 = threadIdx.x * 4;
    float4 xv = *(const float4*)(xr + c0);
    float sum = block_sum256(xv.x + xv.y + xv.z + xv.w, sred);
    float mean = sum * (1.f / DD);
    float d0 = xv.x - mean, d1 = xv.y - mean, d2 = xv.z - mean, d3 = xv.w - mean;
    float ss = block_sum256(d0 * d0 + d1 * d1 + d2 * d2 + d3 * d3, sred);
    float rstd = rsqrtf(ss * (1.f / DD) + EPS);
    const float* shp = mod + b * (6 * DD) + segShift * DD;
    const float* scp = mod + b * (6 * DD) + segScale * DD;
    float4 shv = *(const float4*)(shp + c0);
    float4 scv = *(const float4*)(scp + c0);
    float4 hv;
    hv.x = tf32r(d0 * rstd * (1.f + scv.x) + shv.x);
    hv.y = tf32r(d1 * rstd * (1.f + scv.y) + shv.y);
    hv.z = tf32r(d2 * rstd * (1.f + scv.z) + shv.z);
    hv.w = tf32r(d3 * rstd * (1.f + scv.w) + shv.w);
    *(float4*)(h + (size_t)row * DD + c0) = hv;
}

// ---------------- launch -----------------------------------------------------
extern "C" void kernel_launch(void* const* d_in, const int* in_sizes, int n_in,
                              void* d_out, int out_size) {
    const float* x    = (const float*)d_in[0];
    const float* c    = (const float*)d_in[1];
    const float* Wq   = (const float*)d_in[2];
    const float* bq   = (const float*)d_in[3];
    const float* Wkv  = (const float*)d_in[4];
    const float* bkv  = (const float*)d_in[5];
    const float* Wo   = (const float*)d_in[6];
    const float* bo   = (const float*)d_in[7];
    const float* W1   = (const float*)d_in[8];
    const float* b1   = (const float*)d_in[9];
    const float* W2   = (const float*)d_in[10];
    const float* b2   = (const float*)d_in[11];
    const float* Wada = (const float*)d_in[12];
    const float* bada = (const float*)d_in[13];
    float* out = (float*)d_out;

    float *mod, *h, *qb, *kvb, *vt, *ao, *hid, *WTq, *WTkv, *WTo, *WT1, *WT2;
    cudaGetSymbolAddress((void**)&mod,  g_mod);
    cudaGetSymbolAddress((void**)&h,    g_h);
    cudaGetSymbolAddress((void**)&qb,   g_q);
    cudaGetSymbolAddress((void**)&kvb,  g_kv);
    cudaGetSymbolAddress((void**)&vt,   g_vt);
    cudaGetSymbolAddress((void**)&ao,   g_ao);
    cudaGetSymbolAddress((void**)&hid,  g_hid);
    cudaGetSymbolAddress((void**)&WTq,  g_WTq);
    cudaGetSymbolAddress((void**)&WTkv, g_WTkv);
    cudaGetSymbolAddress((void**)&WTo,  g_WTo);
    cudaGetSymbolAddress((void**)&WT1,  g_WT1);
    cudaGetSymbolAddress((void**)&WT2,  g_WT2);

    cudaFuncSetAttribute(mma_gemm<0>, cudaFuncAttributeMaxDynamicSharedMemorySize, SMEM_GEMM);
    cudaFuncSetAttribute(mma_gemm<1>, cudaFuncAttributeMaxDynamicSharedMemorySize, SMEM_GEMM);
    cudaFuncSetAttribute(mma_gemm<2>, cudaFuncAttributeMaxDynamicSharedMemorySize, SMEM_GEMM);
    cudaFuncSetAttribute(mma_gemm<3>, cudaFuncAttributeMaxDynamicSharedMemorySize, SMEM_GEMM);
    cudaFuncSetAttribute(attn_mma_kernel, cudaFuncAttributeMaxDynamicSharedMemorySize, SMEM_ATTN);

    dim3 tb(32, 8);
    transpose_kernel<<<dim3(DD / 32, DD / 32), tb>>>(Wq, WTq, DD, DD);
    transpose_kernel<<<dim3(2 * DD / 32, DD / 32), tb>>>(Wkv, WTkv, DD, 2 * DD);
    transpose_kernel<<<dim3(DD / 32, DD / 32), tb>>>(Wo, WTo, DD, DD);
    transpose_kernel<<<dim3(MLPD / 32, DD / 32), tb>>>(W1, WT1, DD, MLPD);
    transpose_kernel<<<dim3(DD / 32, MLPD / 32), tb>>>(W2, WT2, MLPD, DD);

    // 1. adaLN modulation
    mod_kernel<<<dim3(6 * DD / 256, BB), 256>>>(c, Wada, bada, mod);
    // 2. h = modulate(LN(x))  (tf32-rounded)
    ln_mod_kernel<<<ROWS, 256>>>(x, mod, 0, 1, h);
    // 3. q = h @ Wq + bq  (rounded)
    mma_gemm<3><<<dim3(DD / BN, ROWS / BM), 256, SMEM_GEMM>>>(
        h, WTq, bq, qb, ROWS, DD, DD, nullptr, nullptr);
    // 4. kv = h @ Wkv + bkv  (rounded)
    mma_gemm<3><<<dim3(2 * DD / BN, ROWS / BM), 256, SMEM_GEMM>>>(
        h, WTkv, bkv, kvb, ROWS, 2 * DD, DD, nullptr, nullptr);
    // 4b. V^T extraction
    vtrans_kernel<<<dim3(NN / 32, 2, BB * HH), tb>>>(kvb, vt);
    // 5. attention (tf32 mma)
    attn_mma_kernel<<<dim3(NN / 64, HH, BB), 128, SMEM_ATTN>>>(qb, kvb, vt, ao);
    // 6. x1 = x + g_msa * (ao @ Wo + bo) -> out
    mma_gemm<2><<<dim3(DD / BN, ROWS / BM), 256, SMEM_GEMM>>>(
        ao, WTo, bo, out, ROWS, DD, DD, x, mod + 2 * DD);
    // 7. h2 = modulate(LN(x1))
    ln_mod_kernel<<<ROWS, 256>>>(out, mod, 3, 4, h);
    // 8. hid = gelu(h2 @ W1 + b1)  (rounded)
    mma_gemm<1><<<dim3(MLPD / BN, ROWS / BM), 256, SMEM_GEMM>>>(
        h, WT1, b1, hid, ROWS, MLPD, DD, nullptr, nullptr);
    // 9. out = x1 + g_mlp * (hid @ W2 + b2)
    mma_gemm<2><<<dim3(DD / BN, ROWS / BM), 256, SMEM_GEMM>>>(
        hid, WT2, b2, out, ROWS, DD, MLPD, out, mod + 5 * DD);
}

// round 7
// speedup vs baseline: 4.1318x; 1.0593x over previous
#include <cuda_runtime.h>
#include <cuda_bf16.h>
#include <cstdint>
#include <math.h>

// Problem constants
#define BB 4
#define NN 1024
#define DD 1024
#define HH 16
#define DHD 64
#define MLPD 4096
#define ROWS (BB*NN)          // 4096
#define EPS 1e-6f

// GEMM tiling (128x128 tile, 3-stage, 2 CTAs/SM)
#define BM 128
#define BN 128
#define BK 32
#define STG 3
#define ROWB 144              // 32 floats + 16B pad per row
#define ASTG (BM*ROWB)
#define BSTG (BN*ROWB)
#define STGB (ASTG+BSTG)      // 36864
#define SMEM_GEMM (STG*STGB)  // 110592

// Attention tiling
#define AROWB 272             // 64 floats + 16B pad
#define ASM_Q 0
#define ASM_P 17408
#define ASM_K 34816
#define ASM_V 69632
#define SMEM_ATTN 104448

// ---------------- scratch (device globals) ----------------------------------
__device__ float g_mod[BB * 6 * DD];
__device__ float g_h[ROWS * DD];
__device__ float g_q[ROWS * DD];
__device__ float g_kv[ROWS * 2 * DD];
__device__ float g_vt[BB * HH * DHD * NN];   // V^T: [b][h][dh][key]
__device__ float g_ao[ROWS * DD];
__device__ float g_hid[ROWS * MLPD];
__device__ float g_WTq[DD * DD];
__device__ float g_WTkv[2 * DD * DD];
__device__ float g_WTo[DD * DD];
__device__ float g_WT1[MLPD * DD];
__device__ float g_WT2[DD * MLPD];

// ======================= helpers ============================================
__device__ __forceinline__ uint32_t smem_u32(const void* p) {
    uint32_t a;
    asm("{ .reg .u64 t; cvta.to.shared.u64 t, %1; cvt.u32.u64 %0, t; }"
        : "=r"(a) : "l"(p));
    return a;
}
__device__ __forceinline__ float tf32r(float x) {
    uint32_t u;
    asm("cvt.rna.tf32.f32 %0, %1;" : "=r"(u) : "f"(x));
    return __uint_as_float(u);
}
__device__ __forceinline__ float ex2(float x) {
    float r;
    asm("ex2.approx.ftz.f32 %0, %1;" : "=f"(r) : "f"(x));
    return r;
}
__device__ __forceinline__ void ldsm4(uint32_t* r, uint32_t addr) {
    asm volatile("ldmatrix.sync.aligned.m8n8.x4.shared.b16 {%0,%1,%2,%3}, [%4];"
                 : "=r"(r[0]), "=r"(r[1]), "=r"(r[2]), "=r"(r[3]) : "r"(addr));
}
__device__ __forceinline__ void mma8(float* c, const uint32_t* a, const uint32_t* b) {
    asm volatile(
        "mma.sync.aligned.m16n8k8.row.col.f32.tf32.tf32.f32 "
        "{%0,%1,%2,%3}, {%4,%5,%6,%7}, {%8,%9}, {%0,%1,%2,%3};"
        : "+f"(c[0]), "+f"(c[1]), "+f"(c[2]), "+f"(c[3])
        : "r"(a[0]), "r"(a[1]), "r"(a[2]), "r"(a[3]), "r"(b[0]), "r"(b[1]));
}
__device__ __forceinline__ void cp16(uint32_t dst, const void* src) {
    asm volatile("cp.async.cg.shared.global [%0], [%1], 16;"
                 :: "r"(dst), "l"(src) : "memory");
}

// ===================== weight transpose W[K,N] -> WT[N,K] (tf32-rounded) ====
__global__ void transpose_kernel(const float* __restrict__ W, float* __restrict__ WT,
                                 int K, int N) {
    __shared__ float t[32][33];
    int n0 = blockIdx.x * 32, k0 = blockIdx.y * 32;
    int tx = threadIdx.x, ty = threadIdx.y;  // 32 x 8
    #pragma unroll
    for (int i = 0; i < 32; i += 8)
        t[ty + i][tx] = tf32r(W[(size_t)(k0 + ty + i) * N + n0 + tx]);
    __syncthreads();
    #pragma unroll
    for (int i = 0; i < 32; i += 8)
        WT[(size_t)(n0 + ty + i) * K + k0 + tx] = t[tx][ty + i];
}

// ============ V^T extraction: kv[b*N+key][D + h*64 + dh] -> Vt[b,h,dh][key] ==
__global__ void vtrans_kernel(const float* __restrict__ kv, float* __restrict__ Vt) {
    __shared__ float t[32][33];
    int bh = blockIdx.z, b = bh >> 4, hh = bh & 15;
    int k0 = blockIdx.x * 32, d0 = blockIdx.y * 32;
    int tx = threadIdx.x, ty = threadIdx.y;
    #pragma unroll
    for (int i = 0; i < 32; i += 8)
        t[ty + i][tx] = kv[(size_t)(b * NN + k0 + ty + i) * (2 * DD) + DD + hh * 64 + d0 + tx];
    __syncthreads();
    #pragma unroll
    for (int i = 0; i < 32; i += 8)
        Vt[(size_t)(bh * 64 + d0 + ty + i) * NN + k0 + tx] = t[tx][ty + i];
}

// ============ tf32 mma.sync GEMM: C = A[M,K] @ BT[N,K]^T + bias =============
// EPI: 0 none, 1 gelu+round, 2 residual+gate, 3 round
template <int EPI>
__global__ __launch_bounds__(256, 2)
void mma_gemm(const float* __restrict__ A, const float* __restrict__ BT,
              const float* __restrict__ bias, float* __restrict__ C,
              int M, int N, int K,
              const float* __restrict__ resid, const float* __restrict__ gate) {
    extern __shared__ char smem[];
    uint32_t sb = smem_u32(smem);
    int tid = threadIdx.x, lane = tid & 31, wid = tid >> 5;
    int wm = wid & 1, wn = wid >> 1;            // 2 x 4 grid; warp tile 64x32
    int bm = blockIdx.y * BM, bn = blockIdx.x * BN;

    float acc[4][4][4];
    #pragma unroll
    for (int i = 0; i < 4; i++)
        #pragma unroll
        for (int j = 0; j < 4; j++)
            #pragma unroll
            for (int e = 0; e < 4; e++) acc[i][j][e] = 0.f;

    int r8 = lane & 7;
    uint32_t a_off = (uint32_t)((wm * 64 + ((lane >> 3) & 1) * 8 + r8) * ROWB
                                + (lane >> 4) * 16);
    uint32_t b_off = (uint32_t)((wn * 32 + (lane >> 4) * 8 + r8) * ROWB
                                + ((lane >> 3) & 1) * 16);
    const int nst = K / BK;

    auto load_stage = [&](int s, int buf) {
        uint32_t ab = sb + buf * STGB;
        uint32_t bb = ab + ASTG;
        int ko = s * BK;
        #pragma unroll
        for (int i = 0; i < 4; i++) {
            int idx = tid + 256 * i, row = idx >> 3, c = idx & 7;
            cp16(ab + row * ROWB + c * 16, A + (size_t)(bm + row) * K + ko + c * 4);
        }
        #pragma unroll
        for (int i = 0; i < 4; i++) {
            int idx = tid + 256 * i, row = idx >> 3, c = idx & 7;
            cp16(bb + row * ROWB + c * 16, BT + (size_t)(bn + row) * K + ko + c * 4);
        }
    };

    load_stage(0, 0);
    asm volatile("cp.async.commit_group;" ::: "memory");
    load_stage(1, 1);
    asm volatile("cp.async.commit_group;" ::: "memory");

    for (int s = 0; s < nst; s++) {
        asm volatile("cp.async.wait_group 1;" ::: "memory");
        __syncthreads();
        if (s + 2 < nst) load_stage(s + 2, (s + 2) % STG);
        asm volatile("cp.async.commit_group;" ::: "memory");

        uint32_t ab = sb + (s % STG) * STGB;
        uint32_t bb = ab + ASTG;
        #pragma unroll
        for (int ks = 0; ks < 4; ks++) {
            uint32_t afr[4][4], bfr[2][4];
            #pragma unroll
            for (int i = 0; i < 4; i++)
                ldsm4(afr[i], ab + a_off + i * 16 * ROWB + ks * 32);
            #pragma unroll
            for (int jp = 0; jp < 2; jp++)
                ldsm4(bfr[jp], bb + b_off + jp * 16 * ROWB + ks * 32);
            #pragma unroll
            for (int i = 0; i < 4; i++)
                #pragma unroll
                for (int j = 0; j < 4; j++)
                    mma8(acc[i][j], afr[i], &bfr[j >> 1][(j & 1) * 2]);
        }
    }

    int g = lane >> 2, tg = lane & 3;
    #pragma unroll
    for (int i = 0; i < 4; i++) {
        #pragma unroll
        for (int half = 0; half < 2; half++) {
            int row = bm + wm * 64 + i * 16 + half * 8 + g;
            int bvar = row >> 10;
            #pragma unroll
            for (int j = 0; j < 4; j++) {
                int col = bn + wn * 32 + j * 8 + tg * 2;
                float v0 = acc[i][j][half * 2 + 0] + bias[col];
                float v1 = acc[i][j][half * 2 + 1] + bias[col + 1];
                if (EPI == 1) {
                    float u = v0;
                    v0 = tf32r(0.5f * u * (1.f + tanhf(0.7978845608028654f *
                                                       (u + 0.044715f * u * u * u))));
                    u = v1;
                    v1 = tf32r(0.5f * u * (1.f + tanhf(0.7978845608028654f *
                                                       (u + 0.044715f * u * u * u))));
                } else if (EPI == 2) {
                    float2 rv = *(const float2*)(resid + (size_t)row * N + col);
                    float2 gv = *(const float2*)(gate + bvar * (6 * DD) + col);
                    v0 = rv.x + gv.x * v0;
                    v1 = rv.y + gv.y * v1;
                } else if (EPI == 3) {
                    v0 = tf32r(v0);
                    v1 = tf32r(v1);
                }
                *(float2*)(C + (size_t)row * N + col) = make_float2(v0, v1);
            }
        }
    }
}

// =================== tf32 mma flash attention ===============================
// grid (N/64, H, B), block 128 (4 warps, 16 query rows each), 2 CTAs/SM
__global__ __launch_bounds__(128, 2)
void attn_mma_kernel(const float* __restrict__ q, const float* __restrict__ kv,
                     const float* __restrict__ Vt, float* __restrict__ ao) {
    extern __shared__ char smem[];
    uint32_t sb = smem_u32(smem);
    int tid = threadIdx.x, lane = tid & 31, w = tid >> 5;
    int b = blockIdx.z, hh = blockIdx.y, q0 = blockIdx.x * 64;
    int g = lane >> 2, tg = lane & 3, r8 = lane & 7;

    // Q tile load (group 0, together with K/V tile 0)
    const float* qbase = q + ((size_t)(b * NN + q0)) * DD + hh * 64;
    #pragma unroll
    for (int i = 0; i < 8; i++) {
        int u = tid + 128 * i;
        int row = u >> 4, c16 = u & 15;
        cp16(sb + ASM_Q + row * AROWB + c16 * 16, qbase + (size_t)row * DD + c16 * 4);
    }
    auto load_tile = [&](int t, int buf) {
        const float* kbase = kv + ((size_t)(b * NN + t * 64)) * (2 * DD) + hh * 64;
        const float* vbase = Vt + ((size_t)((b * HH + hh) * 64)) * NN + t * 64;
        #pragma unroll
        for (int i = 0; i < 8; i++) {
            int u = tid + 128 * i;
            int row = u >> 4, c16 = u & 15;
            cp16(sb + ASM_K + buf * 17408 + row * AROWB + c16 * 16,
                 kbase + (size_t)row * (2 * DD) + c16 * 4);
            cp16(sb + ASM_V + buf * 17408 + row * AROWB + c16 * 16,
                 vbase + (size_t)row * NN + c16 * 4);
        }
    };
    load_tile(0, 0);
    asm volatile("cp.async.commit_group;" ::: "memory");
    load_tile(1, 1);
    asm volatile("cp.async.commit_group;" ::: "memory");

    uint32_t a_pat = (uint32_t)(((((lane >> 3) & 1) * 8 + r8)) * AROWB + (lane >> 4) * 16);
    uint32_t q_off = sb + ASM_Q + w * 16 * AROWB + a_pat;
    uint32_t p_off = sb + ASM_P + w * 16 * AROWB + a_pat;
    uint32_t b_pat = (uint32_t)(((lane >> 4) * 8 + r8) * AROWB + ((lane >> 3) & 1) * 16);

    uint32_t afrQ[8][4];
    float oacc[8][4];
    #pragma unroll
    for (int j = 0; j < 8; j++)
        #pragma unroll
        for (int e = 0; e < 4; e++) oacc[j][e] = 0.f;
    float m0 = -1e30f, m1 = -1e30f, l0 = 0.f, l1 = 0.f;
    const float cc = 0.18033688011112042f;  // 0.125 * log2(e)

    for (int t = 0; t < NN / 64; t++) {
        asm volatile("cp.async.wait_group 1;" ::: "memory");
        __syncthreads();
        if (t == 0) {
            #pragma unroll
            for (int ks = 0; ks < 8; ks++) ldsm4(afrQ[ks], q_off + ks * 32);
        }
        uint32_t kb = sb + ASM_K + (t & 1) * 17408;
        uint32_t vb = sb + ASM_V + (t & 1) * 17408;

        // S = Q @ K^T
        float sacc[8][4];
        #pragma unroll
        for (int j = 0; j < 8; j++)
            #pragma unroll
            for (int e = 0; e < 4; e++) sacc[j][e] = 0.f;
        #pragma unroll
        for (int ks = 0; ks < 8; ks++) {
            #pragma unroll
            for (int jp = 0; jp < 4; jp++) {
                uint32_t bfr[4];
                ldsm4(bfr, kb + b_pat + jp * 16 * AROWB + ks * 32);
                mma8(sacc[jp * 2], afrQ[ks], bfr);
                mma8(sacc[jp * 2 + 1], afrQ[ks], bfr + 2);
            }
        }

        // online softmax (base-2)
        float mt0 = -1e30f, mt1 = -1e30f;
        #pragma unroll
        for (int j = 0; j < 8; j++) {
            mt0 = fmaxf(mt0, fmaxf(sacc[j][0], sacc[j][1]));
            mt1 = fmaxf(mt1, fmaxf(sacc[j][2], sacc[j][3]));
        }
        mt0 = fmaxf(mt0, __shfl_xor_sync(0xffffffffu, mt0, 1));
        mt0 = fmaxf(mt0, __shfl_xor_sync(0xffffffffu, mt0, 2));
        mt1 = fmaxf(mt1, __shfl_xor_sync(0xffffffffu, mt1, 1));
        mt1 = fmaxf(mt1, __shfl_xor_sync(0xffffffffu, mt1, 2));
        mt0 *= cc; mt1 *= cc;
        float mn0 = fmaxf(m0, mt0), mn1 = fmaxf(m1, mt1);
        float cor0 = ex2(m0 - mn0), cor1 = ex2(m1 - mn1);
        l0 *= cor0; l1 *= cor1;
        #pragma unroll
        for (int j = 0; j < 8; j++) {
            oacc[j][0] *= cor0; oacc[j][1] *= cor0;
            oacc[j][2] *= cor1; oacc[j][3] *= cor1;
        }
        float s0 = 0.f, s1 = 0.f;
        char* pst = smem + ASM_P + (w * 16 + g) * AROWB + tg * 8;
        #pragma unroll
        for (int j = 0; j < 8; j++) {
            float p00 = ex2(fmaf(sacc[j][0], cc, -mn0));
            float p01 = ex2(fmaf(sacc[j][1], cc, -mn0));
            float p10 = ex2(fmaf(sacc[j][2], cc, -mn1));
            float p11 = ex2(fmaf(sacc[j][3], cc, -mn1));
            s0 += p00 + p01; s1 += p10 + p11;
            *(float2*)(pst + j * 32) = make_float2(tf32r(p00), tf32r(p01));
            *(float2*)(pst + 8 * AROWB + j * 32) = make_float2(tf32r(p10), tf32r(p11));
        }
        s0 += __shfl_xor_sync(0xffffffffu, s0, 1);
        s0 += __shfl_xor_sync(0xffffffffu, s0, 2);
        s1 += __shfl_xor_sync(0xffffffffu, s1, 1);
        s1 += __shfl_xor_sync(0xffffffffu, s1, 2);
        l0 += s0; l1 += s1;
        m0 = mn0; m1 = mn1;
        __syncwarp();

        // O += P @ V^T
        #pragma unroll
        for (int ks = 0; ks < 8; ks++) {
            uint32_t aP[4];
            ldsm4(aP, p_off + ks * 32);
            #pragma unroll
            for (int jp = 0; jp < 4; jp++) {
                uint32_t bfr[4];
                ldsm4(bfr, vb + b_pat + jp * 16 * AROWB + ks * 32);
                mma8(oacc[jp * 2], aP, bfr);
                mma8(oacc[jp * 2 + 1], aP, bfr + 2);
            }
        }
        __syncthreads();
        if (t + 2 < NN / 64) load_tile(t + 2, t & 1);
        asm volatile("cp.async.commit_group;" ::: "memory");
    }

    float rl0 = 1.f / l0, rl1 = 1.f / l1;
    float* aob = ao + ((size_t)(b * NN + q0 + w * 16)) * DD + hh * 64;
    #pragma unroll
    for (int j = 0; j < 8; j++) {
        int col = j * 8 + tg * 2;
        *(float2*)(aob + (size_t)g * DD + col) =
            make_float2(tf32r(oacc[j][0] * rl0), tf32r(oacc[j][1] * rl0));
        *(float2*)(aob + (size_t)(g + 8) * DD + col) =
            make_float2(tf32r(oacc[j][2] * rl1), tf32r(oacc[j][3] * rl1));
    }
}

// ---------------- adaLN modulation ------------------------------------------
__global__ void mod_kernel(const float* __restrict__ c,
                           const float* __restrict__ Wada,
                           const float* __restrict__ bada,
                           float* __restrict__ mod) {
    __shared__ float sc[DD];
    int b = blockIdx.y;
    int j = blockIdx.x * 256 + threadIdx.x;
    for (int k = threadIdx.x; k < DD; k += 256) {
        float v = c[b * DD + k];
        sc[k] = v / (1.f + __expf(-v));
    }
    __syncthreads();
    float acc = bada[j];
    #pragma unroll 4
    for (int k = 0; k < DD; k++) acc += sc[k] * Wada[(size_t)k * (6 * DD) + j];
    mod[b * (6 * DD) + j] = acc;
}

// ---------------- LayerNorm + modulate (tf32-rounded output) -----------------
__device__ __forceinline__ float block_sum256(float v, float* sred) {
    #pragma unroll
    for (int o = 16; o > 0; o >>= 1) v += __shfl_down_sync(0xffffffffu, v, o);
    int lane = threadIdx.x & 31, w = threadIdx.x >> 5;
    if (lane == 0) sred[w] = v;
    __syncthreads();
    if (w == 0) {
        float t = (lane < 8) ? sred[lane] : 0.f;
        #pragma unroll
        for (int o = 4; o > 0; o >>= 1) t += __shfl_down_sync(0xffffffffu, t, o);
        if (lane == 0) sred[0] = t;
    }
    __syncthreads();
    float r = sred[0];
    __syncthreads();
    return r;
}

__global__ void ln_mod_kernel(const float* __restrict__ x,
                              const float* __restrict__ mod,
                              int segShift, int segScale,
                              float* __restrict__ h) {
    __shared__ float sred[8];
    int row = blockIdx.x;
    int b = row >> 10;
    const float* xr = x + (size_t)row * DD;
    int c0 = threadIdx.x * 4;
    float4 xv = *(const float4*)(xr + c0);
    float sum = block_sum256(xv.x + xv.y + xv.z + xv.w, sred);
    float mean = sum * (1.f / DD);
    float d0 = xv.x - mean, d1 = xv.y - mean, d2 = xv.z - mean, d3 = xv.w - mean;
    float ss = block_sum256(d0 * d0 + d1 * d1 + d2 * d2 + d3 * d3, sred);
    float rstd = rsqrtf(ss * (1.f / DD) + EPS);
    const float* shp = mod + b * (6 * DD) + segShift * DD;
    const float* scp = mod + b * (6 * DD) + segScale * DD;
    float4 shv = *(const float4*)(shp + c0);
    float4 scv = *(const float4*)(scp + c0);
    float4 hv;
    hv.x = tf32r(d0 * rstd * (1.f + scv.x) + shv.x);
    hv.y = tf32r(d1 * rstd * (1.f + scv.y) + shv.y);
    hv.z = tf32r(d2 * rstd * (1.f + scv.z) + shv.z);
    hv.w = tf32r(d3 * rstd * (1.f + scv.w) + shv.w);
    *(float4*)(h + (size_t)row * DD + c0) = hv;
}

// ---------------- launch -----------------------------------------------------
extern "C" void kernel_launch(void* const* d_in, const int* in_sizes, int n_in,
                              void* d_out, int out_size) {
    const float* x    = (const float*)d_in[0];
    const float* c    = (const float*)d_in[1];
    const float* Wq   = (const float*)d_in[2];
    const float* bq   = (const float*)d_in[3];
    const float* Wkv  = (const float*)d_in[4];
    const float* bkv  = (const float*)d_in[5];
    const float* Wo   = (const float*)d_in[6];
    const float* bo   = (const float*)d_in[7];
    const float* W1   = (const float*)d_in[8];
    const float* b1   = (const float*)d_in[9];
    const float* W2   = (const float*)d_in[10];
    const float* b2   = (const float*)d_in[11];
    const float* Wada = (const float*)d_in[12];
    const float* bada = (const float*)d_in[13];
    float* out = (float*)d_out;

    float *mod, *h, *qb, *kvb, *vt, *ao, *hid, *WTq, *WTkv, *WTo, *WT1, *WT2;
    cudaGetSymbolAddress((void**)&mod,  g_mod);
    cudaGetSymbolAddress((void**)&h,    g_h);
    cudaGetSymbolAddress((void**)&qb,   g_q);
    cudaGetSymbolAddress((void**)&kvb,  g_kv);
    cudaGetSymbolAddress((void**)&vt,   g_vt);
    cudaGetSymbolAddress((void**)&ao,   g_ao);
    cudaGetSymbolAddress((void**)&hid,  g_hid);
    cudaGetSymbolAddress((void**)&WTq,  g_WTq);
    cudaGetSymbolAddress((void**)&WTkv, g_WTkv);
    cudaGetSymbolAddress((void**)&WTo,  g_WTo);
    cudaGetSymbolAddress((void**)&WT1,  g_WT1);
    cudaGetSymbolAddress((void**)&WT2,  g_WT2);

    cudaFuncSetAttribute(mma_gemm<0>, cudaFuncAttributeMaxDynamicSharedMemorySize, SMEM_GEMM);
    cudaFuncSetAttribute(mma_gemm<1>, cudaFuncAttributeMaxDynamicSharedMemorySize, SMEM_GEMM);
    cudaFuncSetAttribute(mma_gemm<2>, cudaFuncAttributeMaxDynamicSharedMemorySize, SMEM_GEMM);
    cudaFuncSetAttribute(mma_gemm<3>, cudaFuncAttributeMaxDynamicSharedMemorySize, SMEM_GEMM);
    cudaFuncSetAttribute(attn_mma_kernel, cudaFuncAttributeMaxDynamicSharedMemorySize, SMEM_ATTN);

    dim3 tb(32, 8);
    transpose_kernel<<<dim3(DD / 32, DD / 32), tb>>>(Wq, WTq, DD, DD);
    transpose_kernel<<<dim3(2 * DD / 32, DD / 32), tb>>>(Wkv, WTkv, DD, 2 * DD);
    transpose_kernel<<<dim3(DD / 32, DD / 32), tb>>>(Wo, WTo, DD, DD);
    transpose_kernel<<<dim3(MLPD / 32, DD / 32), tb>>>(W1, WT1, DD, MLPD);
    transpose_kernel<<<dim3(DD / 32, MLPD / 32), tb>>>(W2, WT2, MLPD, DD);

    // 1. adaLN modulation
    mod_kernel<<<dim3(6 * DD / 256, BB), 256>>>(c, Wada, bada, mod);
    // 2. h = modulate(LN(x))  (tf32-rounded)
    ln_mod_kernel<<<ROWS, 256>>>(x, mod, 0, 1, h);
    // 3. q = h @ Wq + bq  (rounded)
    mma_gemm<3><<<dim3(DD / BN, ROWS / BM), 256, SMEM_GEMM>>>(
        h, WTq, bq, qb, ROWS, DD, DD, nullptr, nullptr);
    // 4. kv = h @ Wkv + bkv  (rounded)
    mma_gemm<3><<<dim3(2 * DD / BN, ROWS / BM), 256, SMEM_GEMM>>>(
        h, WTkv, bkv, kvb, ROWS, 2 * DD, DD, nullptr, nullptr);
    // 4b. V^T extraction
    vtrans_kernel<<<dim3(NN / 32, 2, BB * HH), tb>>>(kvb, vt);
    // 5. attention (tf32 mma)
    attn_mma_kernel<<<dim3(NN / 64, HH, BB), 128, SMEM_ATTN>>>(qb, kvb, vt, ao);
    // 6. x1 = x + g_msa * (ao @ Wo + bo) -> out
    mma_gemm<2><<<dim3(DD / BN, ROWS / BM), 256, SMEM_GEMM>>>(
        ao, WTo, bo, out, ROWS, DD, DD, x, mod + 2 * DD);
    // 7. h2 = modulate(LN(x1))
    ln_mod_kernel<<<ROWS, 256>>>(out, mod, 3, 4, h);
    // 8. hid = gelu(h2 @ W1 + b1)  (rounded)
    mma_gemm<1><<<dim3(MLPD / BN, ROWS / BM), 256, SMEM_GEMM>>>(
        h, WT1, b1, hid, ROWS, MLPD, DD, nullptr, nullptr);
    // 9. out = x1 + g_mlp * (hid @ W2 + b2)
    mma_gemm<2><<<dim3(DD / BN, ROWS / BM), 256, SMEM_GEMM>>>(
        hid, WT2, b2, out, ROWS, DD, MLPD, out, mod + 5 * DD);
}

// round 8
// speedup vs baseline: 6.4031x; 1.5497x over previous
#include <cuda_runtime.h>
#include <cuda_fp16.h>
#include <cstdint>
#include <math.h>

// Problem constants
#define BB 4
#define NN 1024
#define DD 1024
#define HH 16
#define DHD 64
#define MLPD 4096
#define ROWS (BB*NN)          // 4096
#define EPS 1e-6f

// GEMM tiling (fp16, 128x128 tile, BK=32, 3-stage)
#define BM 128
#define BN 128
#define BK 32
#define STG 3
#define ROWB 80               // 32 halves = 64B + 16B pad
#define ASTG (BM*ROWB)        // 10240
#define BSTG (BN*ROWB)        // 10240
#define STGB (ASTG+BSTG)      // 20480
#define SMEM_GEMM (STG*STGB)  // 61440

// Attention tiling (fp16)
#define AROWB 144             // 64 halves = 128B + 16B pad
#define ATILE (64*AROWB)      // 9216
#define ASM_Q 0
#define ASM_K ATILE
#define ASM_V (ATILE*3)
#define SMEM_ATTN (ATILE*5)   // 46080

// ---------------- scratch (device globals) ----------------------------------
__device__ float  g_mod[BB * 6 * DD];
__device__ __half g_h[ROWS * DD];
__device__ __half g_q[ROWS * DD];
__device__ __half g_kv[ROWS * 2 * DD];
__device__ __half g_vt[BB * HH * DHD * NN];   // V^T: [b][h][dh][key]
__device__ __half g_ao[ROWS * DD];
__device__ __half g_hid[ROWS * MLPD];
__device__ __half g_WTq[DD * DD];
__device__ __half g_WTkv[2 * DD * DD];
__device__ __half g_WTo[DD * DD];
__device__ __half g_WT1[MLPD * DD];
__device__ __half g_WT2[DD * MLPD];

// ======================= helpers ============================================
__device__ __forceinline__ uint32_t smem_u32(const void* p) {
    uint32_t a;
    asm("{ .reg .u64 t; cvta.to.shared.u64 t, %1; cvt.u32.u64 %0, t; }"
        : "=r"(a) : "l"(p));
    return a;
}
__device__ __forceinline__ float ex2(float x) {
    float r;
    asm("ex2.approx.ftz.f32 %0, %1;" : "=f"(r) : "f"(x));
    return r;
}
__device__ __forceinline__ uint32_t packh2(float lo, float hi) {
    uint32_t r;
    asm("cvt.rn.f16x2.f32 %0, %1, %2;" : "=r"(r) : "f"(hi), "f"(lo));
    return r;
}
__device__ __forceinline__ void ldsm4(uint32_t* r, uint32_t addr) {
    asm volatile("ldmatrix.sync.aligned.m8n8.x4.shared.b16 {%0,%1,%2,%3}, [%4];"
                 : "=r"(r[0]), "=r"(r[1]), "=r"(r[2]), "=r"(r[3]) : "r"(addr));
}
__device__ __forceinline__ void mma16(float* c, const uint32_t* a, const uint32_t* b) {
    asm volatile(
        "mma.sync.aligned.m16n8k16.row.col.f32.f16.f16.f32 "
        "{%0,%1,%2,%3}, {%4,%5,%6,%7}, {%8,%9}, {%0,%1,%2,%3};"
        : "+f"(c[0]), "+f"(c[1]), "+f"(c[2]), "+f"(c[3])
        : "r"(a[0]), "r"(a[1]), "r"(a[2]), "r"(a[3]), "r"(b[0]), "r"(b[1]));
}
__device__ __forceinline__ void cp16(uint32_t dst, const void* src) {
    asm volatile("cp.async.cg.shared.global [%0], [%1], 16;"
                 :: "r"(dst), "l"(src) : "memory");
}

// ===================== weight transpose W[K,N] fp32 -> WT[N,K] fp16 =========
__global__ void transpose_kernel(const float* __restrict__ W, __half* __restrict__ WT,
                                 int K, int N) {
    __shared__ float t[32][33];
    int n0 = blockIdx.x * 32, k0 = blockIdx.y * 32;
    int tx = threadIdx.x, ty = threadIdx.y;  // 32 x 8
    #pragma unroll
    for (int i = 0; i < 32; i += 8)
        t[ty + i][tx] = W[(size_t)(k0 + ty + i) * N + n0 + tx];
    __syncthreads();
    #pragma unroll
    for (int i = 0; i < 32; i += 8)
        WT[(size_t)(n0 + ty + i) * K + k0 + tx] = __float2half_rn(t[tx][ty + i]);
}

// ============ V^T extraction: kv[b*N+key][D + h*64 + dh] -> Vt[bh][dh][key] ==
__global__ void vtrans_kernel(const __half* __restrict__ kv, __half* __restrict__ Vt) {
    __shared__ __half t[32][34];
    int bh = blockIdx.z, b = bh >> 4, hh = bh & 15;
    int k0 = blockIdx.x * 32, d0 = blockIdx.y * 32;
    int tx = threadIdx.x, ty = threadIdx.y;
    #pragma unroll
    for (int i = 0; i < 32; i += 8)
        t[ty + i][tx] = kv[(size_t)(b * NN + k0 + ty + i) * (2 * DD) + DD + hh * 64 + d0 + tx];
    __syncthreads();
    #pragma unroll
    for (int i = 0; i < 32; i += 8)
        Vt[(size_t)(bh * 64 + d0 + ty + i) * NN + k0 + tx] = t[tx][ty + i];
}

// ============ fp16 mma.sync GEMM: C = A[M,K] @ BT[N,K]^T + bias =============
// EPI: 1 gelu -> half, 2 resid+gate -> float, 3 bias -> half
template <int EPI>
__global__ __launch_bounds__(256, 2)
void mma_gemm(const __half* __restrict__ A, const __half* __restrict__ BT,
              const float* __restrict__ bias, void* __restrict__ Cv,
              int M, int N, int K,
              const float* __restrict__ resid, const float* __restrict__ gate) {
    extern __shared__ char smem[];
    uint32_t sb = smem_u32(smem);
    int tid = threadIdx.x, lane = tid & 31, wid = tid >> 5;
    int wm = wid & 1, wn = wid >> 1;            // 2 x 4 grid; warp tile 64x32
    int bm = blockIdx.y * BM, bn = blockIdx.x * BN;

    float acc[4][4][4];
    #pragma unroll
    for (int i = 0; i < 4; i++)
        #pragma unroll
        for (int j = 0; j < 4; j++)
            #pragma unroll
            for (int e = 0; e < 4; e++) acc[i][j][e] = 0.f;

    // A frag: lanes0-7 rows0-7@k0, 8-15 rows8-15@k0, 16-23 rows0-7@+16B, 24-31 rows8-15@+16B
    uint32_t a_pat = (uint32_t)((lane & 15) * ROWB + (lane >> 4) * 16);
    // B frag: lanes0-7 n0-7@k0, 8-15 n0-7@+16B, 16-23 n8-15@k0, 24-31 n8-15@+16B
    uint32_t b_pat = (uint32_t)(((lane & 7) + ((lane >> 4) << 3)) * ROWB
                                + ((lane >> 3) & 1) * 16);
    uint32_t a_off = (uint32_t)(wm * 64) * ROWB + a_pat;
    uint32_t b_off = (uint32_t)(wn * 32) * ROWB + b_pat;
    const int nst = K / BK;

    auto load_stage = [&](int s, int buf) {
        uint32_t ab = sb + buf * STGB;
        uint32_t bb = ab + ASTG;
        int ko = s * BK;
        #pragma unroll
        for (int i = 0; i < 2; i++) {
            int idx = tid + 256 * i, row = idx >> 2, c = idx & 3;
            cp16(ab + row * ROWB + c * 16, A + (size_t)(bm + row) * K + ko + c * 8);
        }
        #pragma unroll
        for (int i = 0; i < 2; i++) {
            int idx = tid + 256 * i, row = idx >> 2, c = idx & 3;
            cp16(bb + row * ROWB + c * 16, BT + (size_t)(bn + row) * K + ko + c * 8);
        }
    };

    load_stage(0, 0);
    asm volatile("cp.async.commit_group;" ::: "memory");
    load_stage(1, 1);
    asm volatile("cp.async.commit_group;" ::: "memory");

    for (int s = 0; s < nst; s++) {
        asm volatile("cp.async.wait_group 1;" ::: "memory");
        __syncthreads();
        if (s + 2 < nst) load_stage(s + 2, (s + 2) % STG);
        asm volatile("cp.async.commit_group;" ::: "memory");

        uint32_t ab = sb + (s % STG) * STGB;
        uint32_t bb = ab + ASTG;
        #pragma unroll
        for (int ks = 0; ks < 2; ks++) {           // two k16 slices per BK=32
            uint32_t afr[4][4], bfr[2][4];
            #pragma unroll
            for (int i = 0; i < 4; i++)
                ldsm4(afr[i], ab + a_off + i * 16 * ROWB + ks * 32);
            #pragma unroll
            for (int jp = 0; jp < 2; jp++)         // two n16 groups (n32)
                ldsm4(bfr[jp], bb + b_off + jp * 16 * ROWB + ks * 32);
            #pragma unroll
            for (int i = 0; i < 4; i++)
                #pragma unroll
                for (int j = 0; j < 4; j++)
                    mma16(acc[i][j], afr[i], &bfr[j >> 1][(j & 1) * 2]);
        }
    }

    int g = lane >> 2, tg = lane & 3;
    #pragma unroll
    for (int i = 0; i < 4; i++) {
        #pragma unroll
        for (int half_ = 0; half_ < 2; half_++) {
            int row = bm + wm * 64 + i * 16 + half_ * 8 + g;
            int bvar = row >> 10;
            #pragma unroll
            for (int j = 0; j < 4; j++) {
                int col = bn + wn * 32 + j * 8 + tg * 2;
                float v0 = acc[i][j][half_ * 2 + 0] + bias[col];
                float v1 = acc[i][j][half_ * 2 + 1] + bias[col + 1];
                if (EPI == 1) {
                    float u = v0;
                    v0 = 0.5f * u * (1.f + tanhf(0.7978845608028654f *
                                                 (u + 0.044715f * u * u * u)));
                    u = v1;
                    v1 = 0.5f * u * (1.f + tanhf(0.7978845608028654f *
                                                 (u + 0.044715f * u * u * u)));
                } else if (EPI == 2) {
                    float2 rv = *(const float2*)(resid + (size_t)row * N + col);
                    float2 gv = *(const float2*)(gate + bvar * (6 * DD) + col);
                    v0 = rv.x + gv.x * v0;
                    v1 = rv.y + gv.y * v1;
                }
                if (EPI == 2) {
                    *(float2*)((float*)Cv + (size_t)row * N + col) = make_float2(v0, v1);
                } else {
                    uint32_t p = packh2(v0, v1);
                    *(uint32_t*)((__half*)Cv + (size_t)row * N + col) = p;
                }
            }
        }
    }
}

// =================== fp16 mma flash attention ===============================
// grid (N/64, H, B), block 128 (4 warps, 16 query rows each)
__global__ __launch_bounds__(128, 3)
void attn_mma_kernel(const __half* __restrict__ q, const __half* __restrict__ kv,
                     const __half* __restrict__ Vt, __half* __restrict__ ao) {
    extern __shared__ char smem[];
    uint32_t sb = smem_u32(smem);
    int tid = threadIdx.x, lane = tid & 31, w = tid >> 5;
    int b = blockIdx.z, hh = blockIdx.y, q0 = blockIdx.x * 64;
    int g = lane >> 2, tg = lane & 3;

    // Q tile load (64 rows x 128B)
    const __half* qbase = q + ((size_t)(b * NN + q0)) * DD + hh * 64;
    #pragma unroll
    for (int i = 0; i < 4; i++) {
        int u = tid + 128 * i;
        int row = u >> 3, c = u & 7;
        cp16(sb + ASM_Q + row * AROWB + c * 16, qbase + (size_t)row * DD + c * 8);
    }
    auto load_tile = [&](int t, int buf) {
        const __half* kbase = kv + ((size_t)(b * NN + t * 64)) * (2 * DD) + hh * 64;
        const __half* vbase = Vt + ((size_t)((b * HH + hh) * 64)) * NN + t * 64;
        #pragma unroll
        for (int i = 0; i < 4; i++) {
            int u = tid + 128 * i;
            int row = u >> 3, c = u & 7;
            cp16(sb + ASM_K + buf * ATILE + row * AROWB + c * 16,
                 kbase + (size_t)row * (2 * DD) + c * 8);
            cp16(sb + ASM_V + buf * ATILE + row * AROWB + c * 16,
                 vbase + (size_t)row * NN + c * 8);
        }
    };
    load_tile(0, 0);
    asm volatile("cp.async.commit_group;" ::: "memory");
    load_tile(1, 1);
    asm volatile("cp.async.commit_group;" ::: "memory");

    uint32_t a_pat = (uint32_t)((lane & 15) * AROWB + (lane >> 4) * 16);
    uint32_t b_pat = (uint32_t)(((lane & 7) + ((lane >> 4) << 3)) * AROWB
                                + ((lane >> 3) & 1) * 16);
    uint32_t q_off = sb + ASM_Q + w * 16 * AROWB + a_pat;

    uint32_t afrQ[4][4];
    float oacc[8][4];
    #pragma unroll
    for (int j = 0; j < 8; j++)
        #pragma unroll
        for (int e = 0; e < 4; e++) oacc[j][e] = 0.f;
    float m0 = -1e30f, m1 = -1e30f, l0 = 0.f, l1 = 0.f;
    const float cc = 0.18033688011112042f;  // 0.125 * log2(e)

    for (int t = 0; t < NN / 64; t++) {
        asm volatile("cp.async.wait_group 1;" ::: "memory");
        __syncthreads();
        if (t == 0) {
            #pragma unroll
            for (int ks = 0; ks < 4; ks++) ldsm4(afrQ[ks], q_off + ks * 32);
        }
        uint32_t kb = sb + ASM_K + (t & 1) * ATILE;
        uint32_t vb = sb + ASM_V + (t & 1) * ATILE;

        // S = Q @ K^T  (n = 64 keys = 8 n8 blocks; k = dh 64 = 4 k16 slices)
        float sacc[8][4];
        #pragma unroll
        for (int j = 0; j < 8; j++)
            #pragma unroll
            for (int e = 0; e < 4; e++) sacc[j][e] = 0.f;
        #pragma unroll
        for (int ks = 0; ks < 4; ks++) {
            #pragma unroll
            for (int jp = 0; jp < 4; jp++) {
                uint32_t bfr[4];
                ldsm4(bfr, kb + b_pat + jp * 16 * AROWB + ks * 32);
                mma16(sacc[jp * 2], afrQ[ks], bfr);
                mma16(sacc[jp * 2 + 1], afrQ[ks], bfr + 2);
            }
        }

        // online softmax (base-2)
        float mt0 = -1e30f, mt1 = -1e30f;
        #pragma unroll
        for (int j = 0; j < 8; j++) {
            mt0 = fmaxf(mt0, fmaxf(sacc[j][0], sacc[j][1]));
            mt1 = fmaxf(mt1, fmaxf(sacc[j][2], sacc[j][3]));
        }
        mt0 = fmaxf(mt0, __shfl_xor_sync(0xffffffffu, mt0, 1));
        mt0 = fmaxf(mt0, __shfl_xor_sync(0xffffffffu, mt0, 2));
        mt1 = fmaxf(mt1, __shfl_xor_sync(0xffffffffu, mt1, 1));
        mt1 = fmaxf(mt1, __shfl_xor_sync(0xffffffffu, mt1, 2));
        mt0 *= cc; mt1 *= cc;
        float mn0 = fmaxf(m0, mt0), mn1 = fmaxf(m1, mt1);
        float cor0 = ex2(m0 - mn0), cor1 = ex2(m1 - mn1);
        l0 *= cor0; l1 *= cor1;
        #pragma unroll
        for (int j = 0; j < 8; j++) {
            oacc[j][0] *= cor0; oacc[j][1] *= cor0;
            oacc[j][2] *= cor1; oacc[j][3] *= cor1;
        }
        float s0 = 0.f, s1 = 0.f;
        float p[8][4];
        #pragma unroll
        for (int j = 0; j < 8; j++) {
            p[j][0] = ex2(fmaf(sacc[j][0], cc, -mn0));
            p[j][1] = ex2(fmaf(sacc[j][1], cc, -mn0));
            p[j][2] = ex2(fmaf(sacc[j][2], cc, -mn1));
            p[j][3] = ex2(fmaf(sacc[j][3], cc, -mn1));
            s0 += p[j][0] + p[j][1]; s1 += p[j][2] + p[j][3];
        }
        s0 += __shfl_xor_sync(0xffffffffu, s0, 1);
        s0 += __shfl_xor_sync(0xffffffffu, s0, 2);
        s1 += __shfl_xor_sync(0xffffffffu, s1, 1);
        s1 += __shfl_xor_sync(0xffffffffu, s1, 2);
        l0 += s0; l1 += s1;
        m0 = mn0; m1 = mn1;

        // O += P @ V^T : P accumulator packs DIRECTLY into A-fragment (no smem)
        #pragma unroll
        for (int s = 0; s < 4; s++) {              // k16 slices over keys
            uint32_t aP[4];
            aP[0] = packh2(p[2 * s][0],     p[2 * s][1]);
            aP[1] = packh2(p[2 * s][2],     p[2 * s][3]);
            aP[2] = packh2(p[2 * s + 1][0], p[2 * s + 1][1]);
            aP[3] = packh2(p[2 * s + 1][2], p[2 * s + 1][3]);
            #pragma unroll
            for (int jp = 0; jp < 4; jp++) {       // n16 groups over dh 64
                uint32_t bfr[4];
                ldsm4(bfr, vb + b_pat + jp * 16 * AROWB + s * 32);
                mma16(oacc[jp * 2], aP, bfr);
                mma16(oacc[jp * 2 + 1], aP, bfr + 2);
            }
        }
        __syncthreads();
        if (t + 2 < NN / 64) load_tile(t + 2, t & 1);
        asm volatile("cp.async.commit_group;" ::: "memory");
    }

    float rl0 = 1.f / l0, rl1 = 1.f / l1;
    __half* aob = ao + ((size_t)(b * NN + q0 + w * 16)) * DD + hh * 64;
    #pragma unroll
    for (int j = 0; j < 8; j++) {
        int col = j * 8 + tg * 2;
        *(uint32_t*)(aob + (size_t)g * DD + col) =
            packh2(oacc[j][0] * rl0, oacc[j][1] * rl0);
        *(uint32_t*)(aob + (size_t)(g + 8) * DD + col) =
            packh2(oacc[j][2] * rl1, oacc[j][3] * rl1);
    }
}

// ---------------- adaLN modulation (fp32) ------------------------------------
__global__ void mod_kernel(const float* __restrict__ c,
                           const float* __restrict__ Wada,
                           const float* __restrict__ bada,
                           float* __restrict__ mod) {
    __shared__ float sc[DD];
    int b = blockIdx.y;
    int j = blockIdx.x * 256 + threadIdx.x;
    for (int k = threadIdx.x; k < DD; k += 256) {
        float v = c[b * DD + k];
        sc[k] = v / (1.f + __expf(-v));
    }
    __syncthreads();
    float acc = bada[j];
    #pragma unroll 4
    for (int k = 0; k < DD; k++) acc += sc[k] * Wada[(size_t)k * (6 * DD) + j];
    mod[b * (6 * DD) + j] = acc;
}

// ---------------- LayerNorm + modulate -> fp16 -------------------------------
__device__ __forceinline__ float block_sum256(float v, float* sred) {
    #pragma unroll
    for (int o = 16; o > 0; o >>= 1) v += __shfl_down_sync(0xffffffffu, v, o);
    int lane = threadIdx.x & 31, w = threadIdx.x >> 5;
    if (lane == 0) sred[w] = v;
    __syncthreads();
    if (w == 0) {
        float t = (lane < 8) ? sred[lane] : 0.f;
        #pragma unroll
        for (int o = 4; o > 0; o >>= 1) t += __shfl_down_sync(0xffffffffu, t, o);
        if (lane == 0) sred[0] = t;
    }
    __syncthreads();
    float r = sred[0];
    __syncthreads();
    return r;
}

__global__ void ln_mod_kernel(const float* __restrict__ x,
                              const float* __restrict__ mod,
                              int segShift, int segScale,
                              __half* __restrict__ h) {
    __shared__ float sred[8];
    int row = blockIdx.x;
    int b = row >> 10;
    const float* xr = x + (size_t)row * DD;
    int c0 = threadIdx.x * 4;
    float4 xv = *(const float4*)(xr + c0);
    float sum = block_sum256(xv.x + xv.y + xv.z + xv.w, sred);
    float mean = sum * (1.f / DD);
    float d0 = xv.x - mean, d1 = xv.y - mean, d2 = xv.z - mean, d3 = xv.w - mean;
    float ss = block_sum256(d0 * d0 + d1 * d1 + d2 * d2 + d3 * d3, sred);
    float rstd = rsqrtf(ss * (1.f / DD) + EPS);
    const float* shp = mod + b * (6 * DD) + segShift * DD;
    const float* scp = mod + b * (6 * DD) + segScale * DD;
    float4 shv = *(const float4*)(shp + c0);
    float4 scv = *(const float4*)(scp + c0);
    uint32_t p0 = packh2(d0 * rstd * (1.f + scv.x) + shv.x,
                         d1 * rstd * (1.f + scv.y) + shv.y);
    uint32_t p1 = packh2(d2 * rstd * (1.f + scv.z) + shv.z,
                         d3 * rstd * (1.f + scv.w) + shv.w);
    *(uint32_t*)(h + (size_t)row * DD + c0) = p0;
    *(uint32_t*)(h + (size_t)row * DD + c0 + 2) = p1;
}

// ---------------- launch -----------------------------------------------------
extern "C" void kernel_launch(void* const* d_in, const int* in_sizes, int n_in,
                              void* d_out, int out_size) {
    const float* x    = (const float*)d_in[0];
    const float* c    = (const float*)d_in[1];
    const float* Wq   = (const float*)d_in[2];
    const float* bq   = (const float*)d_in[3];
    const float* Wkv  = (const float*)d_in[4];
    const float* bkv  = (const float*)d_in[5];
    const float* Wo   = (const float*)d_in[6];
    const float* bo   = (const float*)d_in[7];
    const float* W1   = (const float*)d_in[8];
    const float* b1   = (const float*)d_in[9];
    const float* W2   = (const float*)d_in[10];
    const float* b2   = (const float*)d_in[11];
    const float* Wada = (const float*)d_in[12];
    const float* bada = (const float*)d_in[13];
    float* out = (float*)d_out;

    float* mod;
    __half *h, *qb, *kvb, *vt, *ao, *hid, *WTq, *WTkv, *WTo, *WT1, *WT2;
    cudaGetSymbolAddress((void**)&mod,  g_mod);
    cudaGetSymbolAddress((void**)&h,    g_h);
    cudaGetSymbolAddress((void**)&qb,   g_q);
    cudaGetSymbolAddress((void**)&kvb,  g_kv);
    cudaGetSymbolAddress((void**)&vt,   g_vt);
    cudaGetSymbolAddress((void**)&ao,   g_ao);
    cudaGetSymbolAddress((void**)&hid,  g_hid);
    cudaGetSymbolAddress((void**)&WTq,  g_WTq);
    cudaGetSymbolAddress((void**)&WTkv, g_WTkv);
    cudaGetSymbolAddress((void**)&WTo,  g_WTo);
    cudaGetSymbolAddress((void**)&WT1,  g_WT1);
    cudaGetSymbolAddress((void**)&WT2,  g_WT2);

    cudaFuncSetAttribute(mma_gemm<1>, cudaFuncAttributeMaxDynamicSharedMemorySize, SMEM_GEMM);
    cudaFuncSetAttribute(mma_gemm<2>, cudaFuncAttributeMaxDynamicSharedMemorySize, SMEM_GEMM);
    cudaFuncSetAttribute(mma_gemm<3>, cudaFuncAttributeMaxDynamicSharedMemorySize, SMEM_GEMM);
    cudaFuncSetAttribute(attn_mma_kernel, cudaFuncAttributeMaxDynamicSharedMemorySize, SMEM_ATTN);

    dim3 tb(32, 8);
    transpose_kernel<<<dim3(DD / 32, DD / 32), tb>>>(Wq, WTq, DD, DD);
    transpose_kernel<<<dim3(2 * DD / 32, DD / 32), tb>>>(Wkv, WTkv, DD, 2 * DD);
    transpose_kernel<<<dim3(DD / 32, DD / 32), tb>>>(Wo, WTo, DD, DD);
    transpose_kernel<<<dim3(MLPD / 32, DD / 32), tb>>>(W1, WT1, DD, MLPD);
    transpose_kernel<<<dim3(DD / 32, MLPD / 32), tb>>>(W2, WT2, MLPD, DD);

    // 1. adaLN modulation
    mod_kernel<<<dim3(6 * DD / 256, BB), 256>>>(c, Wada, bada, mod);
    // 2. h = modulate(LN(x)) -> fp16
    ln_mod_kernel<<<ROWS, 256>>>(x, mod, 0, 1, h);
    // 3. q = h @ Wq + bq -> fp16
    mma_gemm<3><<<dim3(DD / BN, ROWS / BM), 256, SMEM_GEMM>>>(
        h, WTq, bq, qb, ROWS, DD, DD, nullptr, nullptr);
    // 4. kv = h @ Wkv + bkv -> fp16
    mma_gemm<3><<<dim3(2 * DD / BN, ROWS / BM), 256, SMEM_GEMM>>>(
        h, WTkv, bkv, kvb, ROWS, 2 * DD, DD, nullptr, nullptr);
    // 4b. V^T extraction
    vtrans_kernel<<<dim3(NN / 32, 2, BB * HH), tb>>>(kvb, vt);
    // 5. attention (fp16 mma)
    attn_mma_kernel<<<dim3(NN / 64, HH, BB), 128, SMEM_ATTN>>>(qb, kvb, vt, ao);
    // 6. x1 = x + g_msa * (ao @ Wo + bo) -> out (fp32)
    mma_gemm<2><<<dim3(DD / BN, ROWS / BM), 256, SMEM_GEMM>>>(
        ao, WTo, bo, out, ROWS, DD, DD, x, mod + 2 * DD);
    // 7. h2 = modulate(LN(x1)) -> fp16
    ln_mod_kernel<<<ROWS, 256>>>(out, mod, 3, 4, h);
    // 8. hid = gelu(h2 @ W1 + b1) -> fp16
    mma_gemm<1><<<dim3(MLPD / BN, ROWS / BM), 256, SMEM_GEMM>>>(
        h, WT1, b1, hid, ROWS, MLPD, DD, nullptr, nullptr);
    // 9. out = x1 + g_mlp * (hid @ W2 + b2) (fp32, in-place residual)
    mma_gemm<2><<<dim3(DD / BN, ROWS / BM), 256, SMEM_GEMM>>>(
        hid, WT2, b2, out, ROWS, DD, MLPD, out, mod + 5 * DD);
}

// round 9
// speedup vs baseline: 6.8160x; 1.0645x over previous
#include <cuda_runtime.h>
#include <cuda_fp16.h>
#include <cstdint>
#include <math.h>

// Problem constants
#define BB 4
#define NN 1024
#define DD 1024
#define HH 16
#define DHD 64
#define MLPD 4096
#define ROWS (BB*NN)          // 4096
#define EPS 1e-6f

// GEMM tiling (fp16, 128x128 tile, BK=64, 3-stage)
#define BM 128
#define BN 128
#define BK 64
#define STG 3
#define ROWB 144              // 64 halves = 128B + 16B pad
#define ASTG (BM*ROWB)        // 18432
#define BSTG (BN*ROWB)        // 18432
#define STGB (ASTG+BSTG)      // 36864
#define SMEM_GEMM (STG*STGB)  // 110592

// Attention tiling (fp16)
#define AROWB 144             // 64 halves = 128B + 16B pad
#define ATILE (64*AROWB)      // 9216
#define ASM_Q 0
#define ASM_K ATILE
#define ASM_V (ATILE*3)
#define SMEM_ATTN (ATILE*5)   // 46080

// ---------------- scratch (device globals) ----------------------------------
__device__ float  g_mod[BB * 6 * DD];
__device__ __half g_h[ROWS * DD];
__device__ __half g_q[ROWS * DD];
__device__ __half g_kv[ROWS * 2 * DD];
__device__ __half g_vt[BB * HH * DHD * NN];   // V^T: [b][h][dh][key]
__device__ __half g_ao[ROWS * DD];
__device__ __half g_hid[ROWS * MLPD];
__device__ __half g_WTq[DD * DD];
__device__ __half g_WTkv[2 * DD * DD];
__device__ __half g_WTo[DD * DD];
__device__ __half g_WT1[MLPD * DD];
__device__ __half g_WT2[DD * MLPD];

// ======================= helpers ============================================
__device__ __forceinline__ uint32_t smem_u32(const void* p) {
    uint32_t a;
    asm("{ .reg .u64 t; cvta.to.shared.u64 t, %1; cvt.u32.u64 %0, t; }"
        : "=r"(a) : "l"(p));
    return a;
}
__device__ __forceinline__ float ex2(float x) {
    float r;
    asm("ex2.approx.ftz.f32 %0, %1;" : "=f"(r) : "f"(x));
    return r;
}
__device__ __forceinline__ uint32_t packh2(float lo, float hi) {
    uint32_t r;
    asm("cvt.rn.f16x2.f32 %0, %1, %2;" : "=r"(r) : "f"(hi), "f"(lo));
    return r;
}
__device__ __forceinline__ void ldsm4(uint32_t* r, uint32_t addr) {
    asm volatile("ldmatrix.sync.aligned.m8n8.x4.shared.b16 {%0,%1,%2,%3}, [%4];"
                 : "=r"(r[0]), "=r"(r[1]), "=r"(r[2]), "=r"(r[3]) : "r"(addr));
}
__device__ __forceinline__ void mma16(float* c, const uint32_t* a, const uint32_t* b) {
    asm volatile(
        "mma.sync.aligned.m16n8k16.row.col.f32.f16.f16.f32 "
        "{%0,%1,%2,%3}, {%4,%5,%6,%7}, {%8,%9}, {%0,%1,%2,%3};"
        : "+f"(c[0]), "+f"(c[1]), "+f"(c[2]), "+f"(c[3])
        : "r"(a[0]), "r"(a[1]), "r"(a[2]), "r"(a[3]), "r"(b[0]), "r"(b[1]));
}
__device__ __forceinline__ void cp16(uint32_t dst, const void* src) {
    asm volatile("cp.async.cg.shared.global [%0], [%1], 16;"
                 :: "r"(dst), "l"(src) : "memory");
}

// ===================== weight transpose W[K,N] fp32 -> WT[N,K] fp16 =========
__global__ void transpose_kernel(const float* __restrict__ W, __half* __restrict__ WT,
                                 int K, int N) {
    __shared__ float t[32][33];
    int n0 = blockIdx.x * 32, k0 = blockIdx.y * 32;
    int tx = threadIdx.x, ty = threadIdx.y;  // 32 x 8
    #pragma unroll
    for (int i = 0; i < 32; i += 8)
        t[ty + i][tx] = W[(size_t)(k0 + ty + i) * N + n0 + tx];
    __syncthreads();
    #pragma unroll
    for (int i = 0; i < 32; i += 8)
        WT[(size_t)(n0 + ty + i) * K + k0 + tx] = __float2half_rn(t[tx][ty + i]);
}

// ============ V^T extraction: kv[b*N+key][D + h*64 + dh] -> Vt[bh][dh][key] ==
__global__ void vtrans_kernel(const __half* __restrict__ kv, __half* __restrict__ Vt) {
    __shared__ __half t[32][34];
    int bh = blockIdx.z, b = bh >> 4, hh = bh & 15;
    int k0 = blockIdx.x * 32, d0 = blockIdx.y * 32;
    int tx = threadIdx.x, ty = threadIdx.y;
    #pragma unroll
    for (int i = 0; i < 32; i += 8)
        t[ty + i][tx] = kv[(size_t)(b * NN + k0 + ty + i) * (2 * DD) + DD + hh * 64 + d0 + tx];
    __syncthreads();
    #pragma unroll
    for (int i = 0; i < 32; i += 8)
        Vt[(size_t)(bh * 64 + d0 + ty + i) * NN + k0 + tx] = t[tx][ty + i];
}

// ============ fp16 mma.sync GEMM: C = A[M,K] @ BT[N,K]^T + bias =============
// EPI: 1 gelu -> half, 2 resid+gate -> float, 3 bias -> half
template <int EPI>
__global__ __launch_bounds__(256, 2)
void mma_gemm(const __half* __restrict__ A, const __half* __restrict__ BT,
              const float* __restrict__ bias, void* __restrict__ Cv,
              int M, int N, int K,
              const float* __restrict__ resid, const float* __restrict__ gate) {
    extern __shared__ char smem[];
    uint32_t sb = smem_u32(smem);
    int tid = threadIdx.x, lane = tid & 31, wid = tid >> 5;
    int wm = wid & 1, wn = wid >> 1;            // 2 x 4 grid; warp tile 64x32
    int bm = blockIdx.y * BM, bn = blockIdx.x * BN;

    float acc[4][4][4];
    #pragma unroll
    for (int i = 0; i < 4; i++)
        #pragma unroll
        for (int j = 0; j < 4; j++)
            #pragma unroll
            for (int e = 0; e < 4; e++) acc[i][j][e] = 0.f;

    uint32_t a_pat = (uint32_t)((lane & 15) * ROWB + (lane >> 4) * 16);
    uint32_t b_pat = (uint32_t)(((lane & 7) + ((lane >> 4) << 3)) * ROWB
                                + ((lane >> 3) & 1) * 16);
    uint32_t a_off = (uint32_t)(wm * 64) * ROWB + a_pat;
    uint32_t b_off = (uint32_t)(wn * 32) * ROWB + b_pat;
    const int nst = K / BK;

    auto load_stage = [&](int s, int buf) {
        uint32_t ab = sb + buf * STGB;
        uint32_t bb = ab + ASTG;
        int ko = s * BK;
        #pragma unroll
        for (int i = 0; i < 4; i++) {
            int idx = tid + 256 * i, row = idx >> 3, c = idx & 7;
            cp16(ab + row * ROWB + c * 16, A + (size_t)(bm + row) * K + ko + c * 8);
        }
        #pragma unroll
        for (int i = 0; i < 4; i++) {
            int idx = tid + 256 * i, row = idx >> 3, c = idx & 7;
            cp16(bb + row * ROWB + c * 16, BT + (size_t)(bn + row) * K + ko + c * 8);
        }
    };

    load_stage(0, 0);
    asm volatile("cp.async.commit_group;" ::: "memory");
    load_stage(1, 1);
    asm volatile("cp.async.commit_group;" ::: "memory");

    for (int s = 0; s < nst; s++) {
        asm volatile("cp.async.wait_group 1;" ::: "memory");
        __syncthreads();
        if (s + 2 < nst) load_stage(s + 2, (s + 2) % STG);
        asm volatile("cp.async.commit_group;" ::: "memory");

        uint32_t ab = sb + (s % STG) * STGB;
        uint32_t bb = ab + ASTG;
        #pragma unroll
        for (int ks = 0; ks < 4; ks++) {           // four k16 slices per BK=64
            uint32_t afr[4][4], bfr[2][4];
            #pragma unroll
            for (int i = 0; i < 4; i++)
                ldsm4(afr[i], ab + a_off + i * 16 * ROWB + ks * 32);
            #pragma unroll
            for (int jp = 0; jp < 2; jp++)
                ldsm4(bfr[jp], bb + b_off + jp * 16 * ROWB + ks * 32);
            #pragma unroll
            for (int i = 0; i < 4; i++)
                #pragma unroll
                for (int j = 0; j < 4; j++)
                    mma16(acc[i][j], afr[i], &bfr[j >> 1][(j & 1) * 2]);
        }
    }

    int g = lane >> 2, tg = lane & 3;
    #pragma unroll
    for (int i = 0; i < 4; i++) {
        #pragma unroll
        for (int half_ = 0; half_ < 2; half_++) {
            int row = bm + wm * 64 + i * 16 + half_ * 8 + g;
            int bvar = row >> 10;
            #pragma unroll
            for (int j = 0; j < 4; j++) {
                int col = bn + wn * 32 + j * 8 + tg * 2;
                float v0 = acc[i][j][half_ * 2 + 0] + bias[col];
                float v1 = acc[i][j][half_ * 2 + 1] + bias[col + 1];
                if (EPI == 1) {
                    float u = v0;
                    v0 = 0.5f * u * (1.f + tanhf(0.7978845608028654f *
                                                 (u + 0.044715f * u * u * u)));
                    u = v1;
                    v1 = 0.5f * u * (1.f + tanhf(0.7978845608028654f *
                                                 (u + 0.044715f * u * u * u)));
                } else if (EPI == 2) {
                    float2 rv = *(const float2*)(resid + (size_t)row * N + col);
                    float2 gv = *(const float2*)(gate + bvar * (6 * DD) + col);
                    v0 = rv.x + gv.x * v0;
                    v1 = rv.y + gv.y * v1;
                }
                if (EPI == 2) {
                    *(float2*)((float*)Cv + (size_t)row * N + col) = make_float2(v0, v1);
                } else {
                    uint32_t p = packh2(v0, v1);
                    *(uint32_t*)((__half*)Cv + (size_t)row * N + col) = p;
                }
            }
        }
    }
}

// =================== fp16 mma flash attention ===============================
// grid (N/64, H, B), block 128 (4 warps, 16 query rows each)
__global__ __launch_bounds__(128, 3)
void attn_mma_kernel(const __half* __restrict__ q, const __half* __restrict__ kv,
                     const __half* __restrict__ Vt, __half* __restrict__ ao) {
    extern __shared__ char smem[];
    uint32_t sb = smem_u32(smem);
    int tid = threadIdx.x, lane = tid & 31, w = tid >> 5;
    int b = blockIdx.z, hh = blockIdx.y, q0 = blockIdx.x * 64;
    int g = lane >> 2, tg = lane & 3;

    // Q tile load (64 rows x 128B)
    const __half* qbase = q + ((size_t)(b * NN + q0)) * DD + hh * 64;
    #pragma unroll
    for (int i = 0; i < 4; i++) {
        int u = tid + 128 * i;
        int row = u >> 3, c = u & 7;
        cp16(sb + ASM_Q + row * AROWB + c * 16, qbase + (size_t)row * DD + c * 8);
    }
    auto load_tile = [&](int t, int buf) {
        const __half* kbase = kv + ((size_t)(b * NN + t * 64)) * (2 * DD) + hh * 64;
        const __half* vbase = Vt + ((size_t)((b * HH + hh) * 64)) * NN + t * 64;
        #pragma unroll
        for (int i = 0; i < 4; i++) {
            int u = tid + 128 * i;
            int row = u >> 3, c = u & 7;
            cp16(sb + ASM_K + buf * ATILE + row * AROWB + c * 16,
                 kbase + (size_t)row * (2 * DD) + c * 8);
            cp16(sb + ASM_V + buf * ATILE + row * AROWB + c * 16,
                 vbase + (size_t)row * NN + c * 8);
        }
    };
    load_tile(0, 0);
    asm volatile("cp.async.commit_group;" ::: "memory");
    load_tile(1, 1);
    asm volatile("cp.async.commit_group;" ::: "memory");

    uint32_t a_pat = (uint32_t)((lane & 15) * AROWB + (lane >> 4) * 16);
    uint32_t b_pat = (uint32_t)(((lane & 7) + ((lane >> 4) << 3)) * AROWB
                                + ((lane >> 3) & 1) * 16);
    uint32_t q_off = sb + ASM_Q + w * 16 * AROWB + a_pat;

    uint32_t afrQ[4][4];
    float oacc[8][4];
    #pragma unroll
    for (int j = 0; j < 8; j++)
        #pragma unroll
        for (int e = 0; e < 4; e++) oacc[j][e] = 0.f;
    float m0 = -1e30f, m1 = -1e30f, l0 = 0.f, l1 = 0.f;
    const float cc = 0.18033688011112042f;  // 0.125 * log2(e)

    for (int t = 0; t < NN / 64; t++) {
        asm volatile("cp.async.wait_group 1;" ::: "memory");
        __syncthreads();
        if (t == 0) {
            #pragma unroll
            for (int ks = 0; ks < 4; ks++) ldsm4(afrQ[ks], q_off + ks * 32);
        }
        uint32_t kb = sb + ASM_K + (t & 1) * ATILE;
        uint32_t vb = sb + ASM_V + (t & 1) * ATILE;

        // S = Q @ K^T
        float sacc[8][4];
        #pragma unroll
        for (int j = 0; j < 8; j++)
            #pragma unroll
            for (int e = 0; e < 4; e++) sacc[j][e] = 0.f;
        #pragma unroll
        for (int ks = 0; ks < 4; ks++) {
            #pragma unroll
            for (int jp = 0; jp < 4; jp++) {
                uint32_t bfr[4];
                ldsm4(bfr, kb + b_pat + jp * 16 * AROWB + ks * 32);
                mma16(sacc[jp * 2], afrQ[ks], bfr);
                mma16(sacc[jp * 2 + 1], afrQ[ks], bfr + 2);
            }
        }

        // online softmax (base-2)
        float mt0 = -1e30f, mt1 = -1e30f;
        #pragma unroll
        for (int j = 0; j < 8; j++) {
            mt0 = fmaxf(mt0, fmaxf(sacc[j][0], sacc[j][1]));
            mt1 = fmaxf(mt1, fmaxf(sacc[j][2], sacc[j][3]));
        }
        mt0 = fmaxf(mt0, __shfl_xor_sync(0xffffffffu, mt0, 1));
        mt0 = fmaxf(mt0, __shfl_xor_sync(0xffffffffu, mt0, 2));
        mt1 = fmaxf(mt1, __shfl_xor_sync(0xffffffffu, mt1, 1));
        mt1 = fmaxf(mt1, __shfl_xor_sync(0xffffffffu, mt1, 2));
        mt0 *= cc; mt1 *= cc;
        float mn0 = fmaxf(m0, mt0), mn1 = fmaxf(m1, mt1);
        float cor0 = ex2(m0 - mn0), cor1 = ex2(m1 - mn1);
        l0 *= cor0; l1 *= cor1;
        #pragma unroll
        for (int j = 0; j < 8; j++) {
            oacc[j][0] *= cor0; oacc[j][1] *= cor0;
            oacc[j][2] *= cor1; oacc[j][3] *= cor1;
        }
        float s0 = 0.f, s1 = 0.f;
        float p[8][4];
        #pragma unroll
        for (int j = 0; j < 8; j++) {
            p[j][0] = ex2(fmaf(sacc[j][0], cc, -mn0));
            p[j][1] = ex2(fmaf(sacc[j][1], cc, -mn0));
            p[j][2] = ex2(fmaf(sacc[j][2], cc, -mn1));
            p[j][3] = ex2(fmaf(sacc[j][3], cc, -mn1));
            s0 += p[j][0] + p[j][1]; s1 += p[j][2] + p[j][3];
        }
        s0 += __shfl_xor_sync(0xffffffffu, s0, 1);
        s0 += __shfl_xor_sync(0xffffffffu, s0, 2);
        s1 += __shfl_xor_sync(0xffffffffu, s1, 1);
        s1 += __shfl_xor_sync(0xffffffffu, s1, 2);
        l0 += s0; l1 += s1;
        m0 = mn0; m1 = mn1;

        // O += P @ V^T : P accumulator packs directly into A-fragment
        #pragma unroll
        for (int s = 0; s < 4; s++) {
            uint32_t aP[4];
            aP[0] = packh2(p[2 * s][0],     p[2 * s][1]);
            aP[1] = packh2(p[2 * s][2],     p[2 * s][3]);
            aP[2] = packh2(p[2 * s + 1][0], p[2 * s + 1][1]);
            aP[3] = packh2(p[2 * s + 1][2], p[2 * s + 1][3]);
            #pragma unroll
            for (int jp = 0; jp < 4; jp++) {
                uint32_t bfr[4];
                ldsm4(bfr, vb + b_pat + jp * 16 * AROWB + s * 32);
                mma16(oacc[jp * 2], aP, bfr);
                mma16(oacc[jp * 2 + 1], aP, bfr + 2);
            }
        }
        __syncthreads();
        if (t + 2 < NN / 64) load_tile(t + 2, t & 1);
        asm volatile("cp.async.commit_group;" ::: "memory");
    }

    float rl0 = 1.f / l0, rl1 = 1.f / l1;
    __half* aob = ao + ((size_t)(b * NN + q0 + w * 16)) * DD + hh * 64;
    #pragma unroll
    for (int j = 0; j < 8; j++) {
        int col = j * 8 + tg * 2;
        *(uint32_t*)(aob + (size_t)g * DD + col) =
            packh2(oacc[j][0] * rl0, oacc[j][1] * rl0);
        *(uint32_t*)(aob + (size_t)(g + 8) * DD + col) =
            packh2(oacc[j][2] * rl1, oacc[j][3] * rl1);
    }
}

// ---------------- adaLN modulation (fp32) ------------------------------------
__global__ void mod_kernel(const float* __restrict__ c,
                           const float* __restrict__ Wada,
                           const float* __restrict__ bada,
                           float* __restrict__ mod) {
    __shared__ float sc[DD];
    int b = blockIdx.y;
    int j = blockIdx.x * 256 + threadIdx.x;
    for (int k = threadIdx.x; k < DD; k += 256) {
        float v = c[b * DD + k];
        sc[k] = v / (1.f + __expf(-v));
    }
    __syncthreads();
    float acc = bada[j];
    #pragma unroll 4
    for (int k = 0; k < DD; k++) acc += sc[k] * Wada[(size_t)k * (6 * DD) + j];
    mod[b * (6 * DD) + j] = acc;
}

// ---------------- LayerNorm + modulate -> fp16 -------------------------------
__device__ __forceinline__ float block_sum256(float v, float* sred) {
    #pragma unroll
    for (int o = 16; o > 0; o >>= 1) v += __shfl_down_sync(0xffffffffu, v, o);
    int lane = threadIdx.x & 31, w = threadIdx.x >> 5;
    if (lane == 0) sred[w] = v;
    __syncthreads();
    if (w == 0) {
        float t = (lane < 8) ? sred[lane] : 0.f;
        #pragma unroll
        for (int o = 4; o > 0; o >>= 1) t += __shfl_down_sync(0xffffffffu, t, o);
        if (lane == 0) sred[0] = t;
    }
    __syncthreads();
    float r = sred[0];
    __syncthreads();
    return r;
}

__global__ void ln_mod_kernel(const float* __restrict__ x,
                              const float* __restrict__ mod,
                              int segShift, int segScale,
                              __half* __restrict__ h) {
    __shared__ float sred[8];
    int row = blockIdx.x;
    int b = row >> 10;
    const float* xr = x + (size_t)row * DD;
    int c0 = threadIdx.x * 4;
    float4 xv = *(const float4*)(xr + c0);
    float sum = block_sum256(xv.x + xv.y + xv.z + xv.w, sred);
    float mean = sum * (1.f / DD);
    float d0 = xv.x - mean, d1 = xv.y - mean, d2 = xv.z - mean, d3 = xv.w - mean;
    float ss = block_sum256(d0 * d0 + d1 * d1 + d2 * d2 + d3 * d3, sred);
    float rstd = rsqrtf(ss * (1.f / DD) + EPS);
    const float* shp = mod + b * (6 * DD) + segShift * DD;
    const float* scp = mod + b * (6 * DD) + segScale * DD;
    float4 shv = *(const float4*)(shp + c0);
    float4 scv = *(const float4*)(scp + c0);
    uint32_t p0 = packh2(d0 * rstd * (1.f + scv.x) + shv.x,
                         d1 * rstd * (1.f + scv.y) + shv.y);
    uint32_t p1 = packh2(d2 * rstd * (1.f + scv.z) + shv.z,
                         d3 * rstd * (1.f + scv.w) + shv.w);
    *(uint32_t*)(h + (size_t)row * DD + c0) = p0;
    *(uint32_t*)(h + (size_t)row * DD + c0 + 2) = p1;
}

// ---------------- launch -----------------------------------------------------
extern "C" void kernel_launch(void* const* d_in, const int* in_sizes, int n_in,
                              void* d_out, int out_size) {
    const float* x    = (const float*)d_in[0];
    const float* c    = (const float*)d_in[1];
    const float* Wq   = (const float*)d_in[2];
    const float* bq   = (const float*)d_in[3];
    const float* Wkv  = (const float*)d_in[4];
    const float* bkv  = (const float*)d_in[5];
    const float* Wo   = (const float*)d_in[6];
    const float* bo   = (const float*)d_in[7];
    const float* W1   = (const float*)d_in[8];
    const float* b1   = (const float*)d_in[9];
    const float* W2   = (const float*)d_in[10];
    const float* b2   = (const float*)d_in[11];
    const float* Wada = (const float*)d_in[12];
    const float* bada = (const float*)d_in[13];
    float* out = (float*)d_out;

    float* mod;
    __half *h, *qb, *kvb, *vt, *ao, *hid, *WTq, *WTkv, *WTo, *WT1, *WT2;
    cudaGetSymbolAddress((void**)&mod,  g_mod);
    cudaGetSymbolAddress((void**)&h,    g_h);
    cudaGetSymbolAddress((void**)&qb,   g_q);
    cudaGetSymbolAddress((void**)&kvb,  g_kv);
    cudaGetSymbolAddress((void**)&vt,   g_vt);
    cudaGetSymbolAddress((void**)&ao,   g_ao);
    cudaGetSymbolAddress((void**)&hid,  g_hid);
    cudaGetSymbolAddress((void**)&WTq,  g_WTq);
    cudaGetSymbolAddress((void**)&WTkv, g_WTkv);
    cudaGetSymbolAddress((void**)&WTo,  g_WTo);
    cudaGetSymbolAddress((void**)&WT1,  g_WT1);
    cudaGetSymbolAddress((void**)&WT2,  g_WT2);

    cudaFuncSetAttribute(mma_gemm<1>, cudaFuncAttributeMaxDynamicSharedMemorySize, SMEM_GEMM);
    cudaFuncSetAttribute(mma_gemm<2>, cudaFuncAttributeMaxDynamicSharedMemorySize, SMEM_GEMM);
    cudaFuncSetAttribute(mma_gemm<3>, cudaFuncAttributeMaxDynamicSharedMemorySize, SMEM_GEMM);
    cudaFuncSetAttribute(attn_mma_kernel, cudaFuncAttributeMaxDynamicSharedMemorySize, SMEM_ATTN);

    dim3 tb(32, 8);
    transpose_kernel<<<dim3(DD / 32, DD / 32), tb>>>(Wq, WTq, DD, DD);
    transpose_kernel<<<dim3(2 * DD / 32, DD / 32), tb>>>(Wkv, WTkv, DD, 2 * DD);
    transpose_kernel<<<dim3(DD / 32, DD / 32), tb>>>(Wo, WTo, DD, DD);
    transpose_kernel<<<dim3(MLPD / 32, DD / 32), tb>>>(W1, WT1, DD, MLPD);
    transpose_kernel<<<dim3(DD / 32, MLPD / 32), tb>>>(W2, WT2, MLPD, DD);

    // 1. adaLN modulation
    mod_kernel<<<dim3(6 * DD / 256, BB), 256>>>(c, Wada, bada, mod);
    // 2. h = modulate(LN(x)) -> fp16
    ln_mod_kernel<<<ROWS, 256>>>(x, mod, 0, 1, h);
    // 3. q = h @ Wq + bq -> fp16
    mma_gemm<3><<<dim3(DD / BN, ROWS / BM), 256, SMEM_GEMM>>>(
        h, WTq, bq, qb, ROWS, DD, DD, nullptr, nullptr);
    // 4. kv = h @ Wkv + bkv -> fp16
    mma_gemm<3><<<dim3(2 * DD / BN, ROWS / BM), 256, SMEM_GEMM>>>(
        h, WTkv, bkv, kvb, ROWS, 2 * DD, DD, nullptr, nullptr);
    // 4b. V^T extraction
    vtrans_kernel<<<dim3(NN / 32, 2, BB * HH), tb>>>(kvb, vt);
    // 5. attention (fp16 mma)
    attn_mma_kernel<<<dim3(NN / 64, HH, BB), 128, SMEM_ATTN>>>(qb, kvb, vt, ao);
    // 6. x1 = x + g_msa * (ao @ Wo + bo) -> out (fp32)
    mma_gemm<2><<<dim3(DD / BN, ROWS / BM), 256, SMEM_GEMM>>>(
        ao, WTo, bo, out, ROWS, DD, DD, x, mod + 2 * DD);
    // 7. h2 = modulate(LN(x1)) -> fp16
    ln_mod_kernel<<<ROWS, 256>>>(out, mod, 3, 4, h);
    // 8. hid = gelu(h2 @ W1 + b1) -> fp16
    mma_gemm<1><<<dim3(MLPD / BN, ROWS / BM), 256, SMEM_GEMM>>>(
        h, WT1, b1, hid, ROWS, MLPD, DD, nullptr, nullptr);
    // 9. out = x1 + g_mlp * (hid @ W2 + b2) (fp32, in-place residual)
    mma_gemm<2><<<dim3(DD / BN, ROWS / BM), 256, SMEM_GEMM>>>(
        hid, WT2, b2, out, ROWS, DD, MLPD, out, mod + 5 * DD);
}